// round 2
// baseline (speedup 1.0000x reference)
#include <cuda_runtime.h>
#include <math.h>

#define TOK 4096
#define DIM 2048
#define NH 16
#define NKVH 4
#define HD 128
#define FF 7168
#define SEQ 2048
#define BATCH 2

// ---------------- scratch (static device globals; no allocation allowed) ---
__device__ float g_xn[TOK * DIM];
__device__ float g_q[TOK * NH * HD];
__device__ float g_k[TOK * NKVH * HD];
__device__ float g_v[TOK * NKVH * HD];
__device__ float g_attn[TOK * DIM];
__device__ float g_h[TOK * DIM];
__device__ float g_hn[TOK * DIM];
__device__ float g_act[TOK * FF];
__device__ float g_up[TOK * FF];
__device__ int   g_idx[TOK];
__device__ float g_scale[TOK];
__device__ int   g_nsel;

// ---------------- RMSNorm -------------------------------------------------
__global__ void rmsnorm_kernel(const float* __restrict__ x,
                               const float* __restrict__ w,
                               float* __restrict__ out) {
    const int row = blockIdx.x;
    const float* xr = x + (size_t)row * DIM;
    float ss = 0.f;
    for (int i = threadIdx.x; i < DIM; i += 256) {
        float v = xr[i];
        ss += v * v;
    }
    __shared__ float red[256];
    red[threadIdx.x] = ss;
    __syncthreads();
    for (int off = 128; off > 0; off >>= 1) {
        if (threadIdx.x < off) red[threadIdx.x] += red[threadIdx.x + off];
        __syncthreads();
    }
    float rs = rsqrtf(red[0] / (float)DIM + 1e-5f);
    float* outr = out + (size_t)row * DIM;
    for (int i = threadIdx.x; i < DIM; i += 256)
        outr[i] = xr[i] * rs * w[i];
}

// ---------------- SGEMM: C[M,N] = A[M,K] @ W[N,K]^T (+ modes) -------------
// GATHER: A row = g_idx[row]  (compact MLP input rows)
// SCATTER: C row = g_idx[row], C += g_scale[crow]*acc (MoD scatter-add)
// DYNM: effective M = g_nsel
template <bool GATHER, bool SCATTER, bool DYNM>
__global__ void sgemm_kernel(const float* __restrict__ A,
                             const float* __restrict__ W,
                             float* __restrict__ C,
                             const float* __restrict__ Res,
                             int M, int N, int K) {
    const int Mreal = DYNM ? g_nsel : M;
    const int bm = blockIdx.y * 128;
    if (bm >= Mreal) return;
    const int bn = blockIdx.x * 128;

    __shared__ float As[8][128];
    __shared__ float Ws[8][128];

    const int tid = threadIdx.x;
    const int lrow = tid >> 1;
    const int lq = (tid & 1) * 4;

    const int arow = bm + lrow;
    const float* Aptr = nullptr;
    if (arow < Mreal) {
        int ar = GATHER ? g_idx[arow] : arow;
        Aptr = A + (size_t)ar * K;
    }
    const float* Wptr = W + (size_t)(bn + lrow) * K;

    float acc[8][8];
#pragma unroll
    for (int i = 0; i < 8; i++)
#pragma unroll
        for (int j = 0; j < 8; j++) acc[i][j] = 0.f;

    const int tx = tid & 15, ty = tid >> 4;

    for (int k0 = 0; k0 < K; k0 += 8) {
        float4 av = Aptr ? *(const float4*)(Aptr + k0 + lq)
                         : make_float4(0.f, 0.f, 0.f, 0.f);
        float4 wv = *(const float4*)(Wptr + k0 + lq);
        As[lq + 0][lrow] = av.x; As[lq + 1][lrow] = av.y;
        As[lq + 2][lrow] = av.z; As[lq + 3][lrow] = av.w;
        Ws[lq + 0][lrow] = wv.x; Ws[lq + 1][lrow] = wv.y;
        Ws[lq + 2][lrow] = wv.z; Ws[lq + 3][lrow] = wv.w;
        __syncthreads();
#pragma unroll
        for (int kk = 0; kk < 8; kk++) {
            float ra[8], rb[8];
#pragma unroll
            for (int i = 0; i < 8; i++) ra[i] = As[kk][ty * 8 + i];
#pragma unroll
            for (int j = 0; j < 8; j++) rb[j] = Ws[kk][tx * 8 + j];
#pragma unroll
            for (int i = 0; i < 8; i++)
#pragma unroll
                for (int j = 0; j < 8; j++)
                    acc[i][j] = fmaf(ra[i], rb[j], acc[i][j]);
        }
        __syncthreads();
    }

#pragma unroll
    for (int i = 0; i < 8; i++) {
        int row = bm + ty * 8 + i;
        if (row >= Mreal) continue;
        int crow = SCATTER ? g_idx[row] : row;
        size_t coff = (size_t)crow * N + bn + tx * 8;
        if (SCATTER) {
            float rs = g_scale[crow];
#pragma unroll
            for (int j = 0; j < 8; j++) C[coff + j] += rs * acc[i][j];
        } else if (Res) {
#pragma unroll
            for (int j = 0; j < 8; j++) C[coff + j] = Res[coff + j] + acc[i][j];
        } else {
#pragma unroll
            for (int j = 0; j < 8; j++) C[coff + j] = acc[i][j];
        }
    }
}

// ---------------- RoPE ----------------------------------------------------
__global__ void rope_kernel(float* __restrict__ x, int nHeads) {
    int i = blockIdx.x * blockDim.x + threadIdx.x;
    int total = TOK * nHeads * 64;
    if (i >= total) return;
    int half = i & 63;
    int t = i >> 6;
    int hd = t % nHeads;
    int tok = t / nHeads;
    int pos = tok % SEQ;
    float inv = expf(-logf(10000.f) * (float)half * (1.f / 64.f));
    float ang = (float)pos * inv;
    float c = cosf(ang), s = sinf(ang);
    float* base = x + (size_t)tok * (nHeads * HD) + hd * HD + half;
    float x1 = base[0], x2 = base[64];
    base[0] = x1 * c - x2 * s;
    base[64] = x2 * c + x1 * s;
}

// ---------------- Flash attention (fp32, causal, GQA) ---------------------
// Tiles: 64 q rows x 64 k rows, HD=128. 256 threads.
#define ATTN_SMEM_FLOATS (128 * 65 * 2 + 64 * 128 + 64 * 65 + 64 * 3)

__global__ void attn_kernel(const float* __restrict__ Qm,
                            const float* __restrict__ Km,
                            const float* __restrict__ Vm,
                            float* __restrict__ Om) {
    extern __shared__ float sm[];
    float* Qs = sm;                 // [128][65] transposed: Qs[d*65 + r]
    float* Ks = Qs + 128 * 65;      // [128][65] transposed: Ks[d*65 + c]
    float* Vs = Ks + 128 * 65;      // [64][128]: Vs[kk*128 + d]
    float* Ps = Vs + 64 * 128;      // [64][65]
    float* rowm = Ps + 64 * 65;
    float* rowl = rowm + 64;
    float* rowsc = rowl + 64;

    const int tid = threadIdx.x;
    const int qt = blockIdx.x, h = blockIdx.y, b = blockIdx.z;
    const int kvh = h / (NH / NKVH);
    const int q0 = qt * 64;

    for (int i = tid; i < 64 * 128; i += 256) {
        int r = i >> 7, d = i & 127;
        Qs[d * 65 + r] = Qm[((size_t)(b * SEQ + q0 + r)) * (NH * HD) + h * HD + d];
    }
    if (tid < 64) { rowm[tid] = -1e30f; rowl[tid] = 0.f; }

    float Oacc[32];
#pragma unroll
    for (int j = 0; j < 32; j++) Oacc[j] = 0.f;

    const int rc = tid >> 2;    // phase C row 0..63
    const int cg = tid & 3;     // phase C col group
    const int tx = tid & 15, ty = tid >> 4;

    for (int kt = 0; kt <= qt; kt++) {
        __syncthreads();
        for (int i = tid; i < 64 * 128; i += 256) {
            int c = i >> 7, d = i & 127;
            size_t off = ((size_t)(b * SEQ + kt * 64 + c)) * (NKVH * HD) + kvh * HD + d;
            Ks[d * 65 + c] = Km[off];
            Vs[c * 128 + d] = Vm[off];
        }
        __syncthreads();

        float sacc[4][4];
#pragma unroll
        for (int i = 0; i < 4; i++)
#pragma unroll
            for (int j = 0; j < 4; j++) sacc[i][j] = 0.f;

        for (int kd = 0; kd < 128; kd++) {
            float ra[4], rb[4];
#pragma unroll
            for (int i = 0; i < 4; i++) ra[i] = Qs[kd * 65 + ty * 4 + i];
#pragma unroll
            for (int j = 0; j < 4; j++) rb[j] = Ks[kd * 65 + tx * 4 + j];
#pragma unroll
            for (int i = 0; i < 4; i++)
#pragma unroll
                for (int j = 0; j < 4; j++)
                    sacc[i][j] = fmaf(ra[i], rb[j], sacc[i][j]);
        }
        const float qk_scale = 0.08838834764831845f;  // 1/sqrt(128)
#pragma unroll
        for (int i = 0; i < 4; i++) {
            int gq = q0 + ty * 4 + i;
#pragma unroll
            for (int j = 0; j < 4; j++) {
                int gk = kt * 64 + tx * 4 + j;
                float v = sacc[i][j] * qk_scale;
                if (gk > gq) v = -1e30f;
                Ps[(ty * 4 + i) * 65 + tx * 4 + j] = v;
            }
        }
        __syncthreads();

        if (tid < 64) {
            int r = tid;
            float m0 = rowm[r];
            float mx = m0;
            for (int c = 0; c < 64; c++) mx = fmaxf(mx, Ps[r * 65 + c]);
            float sc = __expf(m0 - mx);
            float sum = 0.f;
            for (int c = 0; c < 64; c++) {
                float p = __expf(Ps[r * 65 + c] - mx);
                Ps[r * 65 + c] = p;
                sum += p;
            }
            rowl[r] = rowl[r] * sc + sum;
            rowm[r] = mx;
            rowsc[r] = sc;
        }
        __syncthreads();

        float sc = rowsc[rc];
#pragma unroll
        for (int j = 0; j < 32; j++) Oacc[j] *= sc;
        for (int kk = 0; kk < 64; kk++) {
            float p = Ps[rc * 65 + kk];
#pragma unroll
            for (int j = 0; j < 32; j++)
                Oacc[j] = fmaf(p, Vs[kk * 128 + cg + 4 * j], Oacc[j]);
        }
    }
    __syncthreads();
    float linv = 1.f / rowl[rc];
    float* optr = Om + ((size_t)(b * SEQ + q0 + rc)) * (NH * HD) + h * HD + cg;
#pragma unroll
    for (int j = 0; j < 32; j++) optr[4 * j] = Oacc[j] * linv;
}

// ---------------- MoD compaction (single block, deterministic) ------------
// mask is int32 (jax bool promoted by the harness dtype set {f32,i32,bf16})
__global__ void compact_kernel(const int* __restrict__ mask,
                               const float* __restrict__ scores) {
    __shared__ int ssum[256];
    __shared__ int base;
    const int t = threadIdx.x;
    if (t == 0) base = 0;
    __syncthreads();
    for (int start = 0; start < TOK; start += 256) {
        int i = start + t;
        int f = (mask[i] != 0) ? 1 : 0;
        g_scale[i] = 0.5f + (scores[i] - 0.5f) * 0.7f;
        ssum[t] = f;
        __syncthreads();
        for (int off = 1; off < 256; off <<= 1) {
            int v = (t >= off) ? ssum[t - off] : 0;
            __syncthreads();
            ssum[t] += v;
            __syncthreads();
        }
        if (f) g_idx[base + ssum[t] - 1] = i;
        __syncthreads();
        if (t == 0) base += ssum[255];
        __syncthreads();
    }
    if (t == 0) g_nsel = base;
}

// ---------------- SiLU(gate) * up  (dynamic row count) --------------------
__global__ void silu_mul_kernel(float* __restrict__ act,
                                const float* __restrict__ up) {
    size_t total = (size_t)g_nsel * FF;
    size_t stride = (size_t)gridDim.x * blockDim.x;
    for (size_t i = (size_t)blockIdx.x * blockDim.x + threadIdx.x; i < total; i += stride) {
        float g = act[i];
        act[i] = (g / (1.f + __expf(-g))) * up[i];
    }
}

// ---------------- residual copy to output ---------------------------------
__global__ void copy_kernel(float* __restrict__ dst, const float* __restrict__ src) {
    int i = blockIdx.x * blockDim.x + threadIdx.x;
    if (i < TOK * DIM / 4)
        ((float4*)dst)[i] = ((const float4*)src)[i];
}

// ---------------- driver ---------------------------------------------------
extern "C" void kernel_launch(void* const* d_in, const int* in_sizes, int n_in,
                              void* d_out, int out_size) {
    const float* hidden = (const float*)d_in[0];
    const int* mask = (const int*)d_in[1];
    const float* tscore = (const float*)d_in[2];
    const float* ln1 = (const float*)d_in[3];
    const float* ln2 = (const float*)d_in[4];
    const float* q_w = (const float*)d_in[5];
    const float* k_w = (const float*)d_in[6];
    const float* v_w = (const float*)d_in[7];
    const float* o_w = (const float*)d_in[8];
    const float* gate_w = (const float*)d_in[9];
    const float* up_w = (const float*)d_in[10];
    const float* down_w = (const float*)d_in[11];
    float* out = (float*)d_out;

    void* p;
    cudaGetSymbolAddress(&p, g_xn);   float* xn = (float*)p;
    cudaGetSymbolAddress(&p, g_q);    float* q = (float*)p;
    cudaGetSymbolAddress(&p, g_k);    float* k = (float*)p;
    cudaGetSymbolAddress(&p, g_v);    float* v = (float*)p;
    cudaGetSymbolAddress(&p, g_attn); float* attn = (float*)p;
    cudaGetSymbolAddress(&p, g_h);    float* h = (float*)p;
    cudaGetSymbolAddress(&p, g_hn);   float* hn = (float*)p;
    cudaGetSymbolAddress(&p, g_act);  float* act = (float*)p;
    cudaGetSymbolAddress(&p, g_up);   float* up = (float*)p;

    cudaFuncSetAttribute(attn_kernel, cudaFuncAttributeMaxDynamicSharedMemorySize,
                         ATTN_SMEM_FLOATS * (int)sizeof(float));

    dim3 blk(256);

    // 1. ln1
    rmsnorm_kernel<<<TOK, blk>>>(hidden, ln1, xn);
    // 2-4. q/k/v projections
    sgemm_kernel<false, false, false><<<dim3(16, 32), blk>>>(xn, q_w, q, nullptr, TOK, NH * HD, DIM);
    sgemm_kernel<false, false, false><<<dim3(4, 32), blk>>>(xn, k_w, k, nullptr, TOK, NKVH * HD, DIM);
    sgemm_kernel<false, false, false><<<dim3(4, 32), blk>>>(xn, v_w, v, nullptr, TOK, NKVH * HD, DIM);
    // 5. RoPE
    rope_kernel<<<(TOK * NH * 64 + 255) / 256, blk>>>(q, NH);
    rope_kernel<<<(TOK * NKVH * 64 + 255) / 256, blk>>>(k, NKVH);
    // 6. attention
    attn_kernel<<<dim3(SEQ / 64, NH, BATCH), blk,
                  ATTN_SMEM_FLOATS * sizeof(float)>>>(q, k, v, attn);
    // 7. o-proj + residual
    sgemm_kernel<false, false, false><<<dim3(16, 32), blk>>>(attn, o_w, h, hidden, TOK, DIM, NH * HD);
    // 8. ln2
    rmsnorm_kernel<<<TOK, blk>>>(h, ln2, hn);
    // 9. MoD compaction
    compact_kernel<<<1, blk>>>(mask, tscore);
    // 10-11. gathered gate/up
    sgemm_kernel<true, false, true><<<dim3(FF / 128, 32), blk>>>(hn, gate_w, act, nullptr, TOK, FF, DIM);
    sgemm_kernel<true, false, true><<<dim3(FF / 128, 32), blk>>>(hn, up_w, up, nullptr, TOK, FF, DIM);
    // 12. silu * up
    silu_mul_kernel<<<2048, blk>>>(act, up);
    // 13. out = h (residual for unselected + base for scatter-add)
    copy_kernel<<<(TOK * DIM / 4 + 255) / 256, blk>>>(out, h);
    // 14. down-proj, scatter-add with per-token MoD scale
    sgemm_kernel<false, true, true><<<dim3(16, 32), blk>>>(act, down_w, out, nullptr, TOK, DIM, FF);
}

// round 5
// speedup vs baseline: 1.5913x; 1.5913x over previous
#include <cuda_runtime.h>
#include <cuda_bf16.h>
#include <mma.h>
#include <stdint.h>
#include <math.h>

using namespace nvcuda;

#define TOK 4096
#define DIM 2048
#define NH 16
#define NKVH 4
#define HD 128
#define FF 7168
#define SEQ 2048
#define BATCH 2

#define GBM 128
#define GBN 64
#define GKC 32
#define GLD 40
#define GEPILD 72
#define GEMM_SMEM_BYTES (((GBM * GLD + GBN * GLD) * 2) * 2 + GBM * GEPILD * 4)

// ---------------- scratch (static device globals; no allocation allowed) ---
__device__ float g_xn[TOK * DIM];
__device__ float g_q[TOK * NH * HD];
__device__ float g_k[TOK * NKVH * HD];
__device__ float g_v[TOK * NKVH * HD];
__device__ float g_attn[TOK * DIM];
__device__ float g_h[TOK * DIM];
__device__ float g_hn[TOK * DIM];
__device__ float g_act[TOK * FF];
__device__ float g_up[TOK * FF];
__device__ int   g_idx[TOK];
__device__ float g_scale[TOK];
__device__ int   g_nsel;

// ---------------- fp32 -> bf16 hi/lo split --------------------------------
__device__ __forceinline__ void dsplit(float v, __nv_bfloat16& hi, __nv_bfloat16& lo) {
    hi = __float2bfloat16(v);
    lo = __float2bfloat16(v - __bfloat162float(hi));
}

// ---------------- WMMA GEMM: C[M,N] = A[M,K] @ W[N,K]^T --------------------
// 3-pass bf16 split (hi*hi + hi*lo + lo*hi), fp32 accumulate.
// gather: A row = g_idx[row]; scatter: C row = g_idx[row], C += scale*acc;
// dynm: effective M = g_nsel.
__global__ __launch_bounds__(256)
void wmma_gemm(const float* __restrict__ A, const float* __restrict__ W,
               float* __restrict__ C, const float* __restrict__ Res,
               int M, int N, int K, int gather, int scatter, int dynm) {
    const int Mreal = dynm ? g_nsel : M;
    const int bm = blockIdx.y * GBM;
    if (bm >= Mreal) return;
    const int bn = blockIdx.x * GBN;

    extern __shared__ char smraw[];
    __nv_bfloat16* Ahi = (__nv_bfloat16*)smraw;
    __nv_bfloat16* Alo = Ahi + GBM * GLD;
    __nv_bfloat16* Whi = Alo + GBM * GLD;
    __nv_bfloat16* Wlo = Whi + GBN * GLD;
    float* Cs = (float*)(Wlo + GBN * GLD);

    const int tid = threadIdx.x;
    const int warp = tid >> 5;
    const int wm = (warp >> 1) * 32;   // 4 warps along M
    const int wn = (warp & 1) * 32;    // 2 warps along N

    wmma::fragment<wmma::accumulator, 16, 16, 16, float> acc[2][2];
    wmma::fill_fragment(acc[0][0], 0.0f);
    wmma::fill_fragment(acc[0][1], 0.0f);
    wmma::fill_fragment(acc[1][0], 0.0f);
    wmma::fill_fragment(acc[1][1], 0.0f);

    for (int k0 = 0; k0 < K; k0 += GKC) {
        // ---- stage A tile (GBM x GKC floats), split to hi/lo bf16 ----
        for (int t = 0; t < 4; t++) {
            int idx = tid + t * 256;          // 0..1023
            int row = idx >> 3;
            int c4 = (idx & 7) * 4;
            int am = bm + row;
            float4 v = make_float4(0.f, 0.f, 0.f, 0.f);
            if (am < Mreal) {
                int ar = gather ? g_idx[am] : am;
                v = *(const float4*)(A + (size_t)ar * K + k0 + c4);
            }
            __nv_bfloat16 h0, l0, h1, l1, h2, l2, h3, l3;
            dsplit(v.x, h0, l0);
            dsplit(v.y, h1, l1);
            dsplit(v.z, h2, l2);
            dsplit(v.w, h3, l3);
            int base = row * GLD + c4;
            Ahi[base + 0] = h0; Ahi[base + 1] = h1; Ahi[base + 2] = h2; Ahi[base + 3] = h3;
            Alo[base + 0] = l0; Alo[base + 1] = l1; Alo[base + 2] = l2; Alo[base + 3] = l3;
        }
        // ---- stage W tile (GBN x GKC floats), split to hi/lo bf16 ----
        for (int t = 0; t < 2; t++) {
            int idx = tid + t * 256;          // 0..511
            int row = idx >> 3;
            int c4 = (idx & 7) * 4;
            float4 v = *(const float4*)(W + (size_t)(bn + row) * K + k0 + c4);
            __nv_bfloat16 h0, l0, h1, l1, h2, l2, h3, l3;
            dsplit(v.x, h0, l0);
            dsplit(v.y, h1, l1);
            dsplit(v.z, h2, l2);
            dsplit(v.w, h3, l3);
            int base = row * GLD + c4;
            Whi[base + 0] = h0; Whi[base + 1] = h1; Whi[base + 2] = h2; Whi[base + 3] = h3;
            Wlo[base + 0] = l0; Wlo[base + 1] = l1; Wlo[base + 2] = l2; Wlo[base + 3] = l3;
        }
        __syncthreads();

        // ---- tensor-core compute: 2 chunks of k=16 ----
        for (int kc = 0; kc < GKC; kc += 16) {
            wmma::fragment<wmma::matrix_a, 16, 16, 16, __nv_bfloat16, wmma::row_major> ah[2], al[2];
            wmma::fragment<wmma::matrix_b, 16, 16, 16, __nv_bfloat16, wmma::col_major> bh[2], bl[2];
            for (int mt = 0; mt < 2; mt++) {
                wmma::load_matrix_sync(ah[mt], Ahi + (wm + mt * 16) * GLD + kc, GLD);
                wmma::load_matrix_sync(al[mt], Alo + (wm + mt * 16) * GLD + kc, GLD);
            }
            for (int nt = 0; nt < 2; nt++) {
                wmma::load_matrix_sync(bh[nt], Whi + (wn + nt * 16) * GLD + kc, GLD);
                wmma::load_matrix_sync(bl[nt], Wlo + (wn + nt * 16) * GLD + kc, GLD);
            }
            for (int mt = 0; mt < 2; mt++) {
                for (int nt = 0; nt < 2; nt++) {
                    wmma::mma_sync(acc[mt][nt], ah[mt], bh[nt], acc[mt][nt]);
                    wmma::mma_sync(acc[mt][nt], ah[mt], bl[nt], acc[mt][nt]);
                    wmma::mma_sync(acc[mt][nt], al[mt], bh[nt], acc[mt][nt]);
                }
            }
        }
        __syncthreads();
    }

    // ---- epilogue through smem C tile ----
    for (int mt = 0; mt < 2; mt++)
        for (int nt = 0; nt < 2; nt++)
            wmma::store_matrix_sync(Cs + (wm + mt * 16) * GEPILD + wn + nt * 16,
                                    acc[mt][nt], GEPILD, wmma::mem_row_major);
    __syncthreads();

    {
        int r = tid >> 1;
        int c0 = (tid & 1) * 32;
        int row = bm + r;
        if (row < Mreal) {
            int crow = scatter ? g_idx[row] : row;
            const float* cr = Cs + r * GEPILD + c0;
            size_t off = (size_t)crow * N + bn + c0;
            if (scatter) {
                float rs = g_scale[crow];
                for (int j = 0; j < 32; j++) C[off + j] += rs * cr[j];
            } else if (Res) {
                for (int j = 0; j < 32; j++) C[off + j] = Res[off + j] + cr[j];
            } else {
                for (int j = 0; j < 32; j++) C[off + j] = cr[j];
            }
        }
    }
}

// ---------------- RMSNorm -------------------------------------------------
__global__ void rmsnorm_kernel(const float* __restrict__ x,
                               const float* __restrict__ w,
                               float* __restrict__ out) {
    const int row = blockIdx.x;
    const float* xr = x + (size_t)row * DIM;
    float ss = 0.f;
    for (int i = threadIdx.x; i < DIM; i += 256) {
        float v = xr[i];
        ss += v * v;
    }
    __shared__ float red[256];
    red[threadIdx.x] = ss;
    __syncthreads();
    for (int off = 128; off > 0; off >>= 1) {
        if (threadIdx.x < off) red[threadIdx.x] += red[threadIdx.x + off];
        __syncthreads();
    }
    float rs = rsqrtf(red[0] / (float)DIM + 1e-5f);
    float* outr = out + (size_t)row * DIM;
    for (int i = threadIdx.x; i < DIM; i += 256)
        outr[i] = xr[i] * rs * w[i];
}

// ---------------- RoPE ----------------------------------------------------
__global__ void rope_kernel(float* __restrict__ x, int nHeads) {
    int i = blockIdx.x * blockDim.x + threadIdx.x;
    int total = TOK * nHeads * 64;
    if (i >= total) return;
    int half = i & 63;
    int t = i >> 6;
    int hd = t % nHeads;
    int tok = t / nHeads;
    int pos = tok % SEQ;
    float inv = expf(-logf(10000.f) * (float)half * (1.f / 64.f));
    float ang = (float)pos * inv;
    float c = cosf(ang), s = sinf(ang);
    float* base = x + (size_t)tok * (nHeads * HD) + hd * HD + half;
    float x1 = base[0], x2 = base[64];
    base[0] = x1 * c - x2 * s;
    base[64] = x2 * c + x1 * s;
}

// ---------------- Flash attention (fp32, causal, GQA) ---------------------
#define ATTN_SMEM_FLOATS (128 * 65 * 2 + 64 * 128 + 64 * 65 + 64 * 3)

__global__ void attn_kernel(const float* __restrict__ Qm,
                            const float* __restrict__ Km,
                            const float* __restrict__ Vm,
                            float* __restrict__ Om) {
    extern __shared__ float sm[];
    float* Qs = sm;                 // [128][65] transposed
    float* Ks = Qs + 128 * 65;      // [128][65] transposed
    float* Vs = Ks + 128 * 65;      // [64][128]
    float* Ps = Vs + 64 * 128;      // [64][65]
    float* rowm = Ps + 64 * 65;
    float* rowl = rowm + 64;
    float* rowsc = rowl + 64;

    const int tid = threadIdx.x;
    const int qt = blockIdx.x, h = blockIdx.y, b = blockIdx.z;
    const int kvh = h / (NH / NKVH);
    const int q0 = qt * 64;

    for (int i = tid; i < 64 * 128; i += 256) {
        int r = i >> 7, d = i & 127;
        Qs[d * 65 + r] = Qm[((size_t)(b * SEQ + q0 + r)) * (NH * HD) + h * HD + d];
    }
    if (tid < 64) { rowm[tid] = -1e30f; rowl[tid] = 0.f; }

    float Oacc[32];
#pragma unroll
    for (int j = 0; j < 32; j++) Oacc[j] = 0.f;

    const int rc = tid >> 2;
    const int cg = tid & 3;
    const int tx = tid & 15, ty = tid >> 4;

    for (int kt = 0; kt <= qt; kt++) {
        __syncthreads();
        for (int i = tid; i < 64 * 128; i += 256) {
            int c = i >> 7, d = i & 127;
            size_t off = ((size_t)(b * SEQ + kt * 64 + c)) * (NKVH * HD) + kvh * HD + d;
            Ks[d * 65 + c] = Km[off];
            Vs[c * 128 + d] = Vm[off];
        }
        __syncthreads();

        float sacc[4][4];
#pragma unroll
        for (int i = 0; i < 4; i++)
#pragma unroll
            for (int j = 0; j < 4; j++) sacc[i][j] = 0.f;

        for (int kd = 0; kd < 128; kd++) {
            float ra[4], rb[4];
#pragma unroll
            for (int i = 0; i < 4; i++) ra[i] = Qs[kd * 65 + ty * 4 + i];
#pragma unroll
            for (int j = 0; j < 4; j++) rb[j] = Ks[kd * 65 + tx * 4 + j];
#pragma unroll
            for (int i = 0; i < 4; i++)
#pragma unroll
                for (int j = 0; j < 4; j++)
                    sacc[i][j] = fmaf(ra[i], rb[j], sacc[i][j]);
        }
        const float qk_scale = 0.08838834764831845f;
#pragma unroll
        for (int i = 0; i < 4; i++) {
            int gq = q0 + ty * 4 + i;
#pragma unroll
            for (int j = 0; j < 4; j++) {
                int gk = kt * 64 + tx * 4 + j;
                float v = sacc[i][j] * qk_scale;
                if (gk > gq) v = -1e30f;
                Ps[(ty * 4 + i) * 65 + tx * 4 + j] = v;
            }
        }
        __syncthreads();

        if (tid < 64) {
            int r = tid;
            float m0 = rowm[r];
            float mx = m0;
            for (int c = 0; c < 64; c++) mx = fmaxf(mx, Ps[r * 65 + c]);
            float sc = __expf(m0 - mx);
            float sum = 0.f;
            for (int c = 0; c < 64; c++) {
                float p = __expf(Ps[r * 65 + c] - mx);
                Ps[r * 65 + c] = p;
                sum += p;
            }
            rowl[r] = rowl[r] * sc + sum;
            rowm[r] = mx;
            rowsc[r] = sc;
        }
        __syncthreads();

        float sc = rowsc[rc];
#pragma unroll
        for (int j = 0; j < 32; j++) Oacc[j] *= sc;
        for (int kk = 0; kk < 64; kk++) {
            float p = Ps[rc * 65 + kk];
#pragma unroll
            for (int j = 0; j < 32; j++)
                Oacc[j] = fmaf(p, Vs[kk * 128 + cg + 4 * j], Oacc[j]);
        }
    }
    __syncthreads();
    float linv = 1.f / rowl[rc];
    float* optr = Om + ((size_t)(b * SEQ + q0 + rc)) * (NH * HD) + h * HD + cg;
#pragma unroll
    for (int j = 0; j < 32; j++) optr[4 * j] = Oacc[j] * linv;
}

// ---------------- MoD compaction (single block, deterministic) ------------
__global__ void compact_kernel(const int* __restrict__ mask,
                               const float* __restrict__ scores) {
    __shared__ int ssum[256];
    __shared__ int base;
    const int t = threadIdx.x;
    if (t == 0) base = 0;
    __syncthreads();
    for (int start = 0; start < TOK; start += 256) {
        int i = start + t;
        int f = (mask[i] != 0) ? 1 : 0;
        g_scale[i] = 0.5f + (scores[i] - 0.5f) * 0.7f;
        ssum[t] = f;
        __syncthreads();
        for (int off = 1; off < 256; off <<= 1) {
            int v = (t >= off) ? ssum[t - off] : 0;
            __syncthreads();
            ssum[t] += v;
            __syncthreads();
        }
        if (f) g_idx[base + ssum[t] - 1] = i;
        __syncthreads();
        if (t == 0) base += ssum[255];
        __syncthreads();
    }
    if (t == 0) g_nsel = base;
}

// ---------------- SiLU(gate) * up  (dynamic row count) --------------------
__global__ void silu_mul_kernel(float* __restrict__ act,
                                const float* __restrict__ up) {
    size_t total = (size_t)g_nsel * FF;
    size_t stride = (size_t)gridDim.x * blockDim.x;
    for (size_t i = (size_t)blockIdx.x * blockDim.x + threadIdx.x; i < total; i += stride) {
        float g = act[i];
        act[i] = (g / (1.f + __expf(-g))) * up[i];
    }
}

// ---------------- residual copy to output ---------------------------------
__global__ void copy_kernel(float* __restrict__ dst, const float* __restrict__ src) {
    int i = blockIdx.x * blockDim.x + threadIdx.x;
    if (i < TOK * DIM / 4)
        ((float4*)dst)[i] = ((const float4*)src)[i];
}

// ---------------- driver ---------------------------------------------------
extern "C" void kernel_launch(void* const* d_in, const int* in_sizes, int n_in,
                              void* d_out, int out_size) {
    const float* hidden = (const float*)d_in[0];
    const int* mask = (const int*)d_in[1];
    const float* tscore = (const float*)d_in[2];
    const float* ln1 = (const float*)d_in[3];
    const float* ln2 = (const float*)d_in[4];
    const float* q_w = (const float*)d_in[5];
    const float* k_w = (const float*)d_in[6];
    const float* v_w = (const float*)d_in[7];
    const float* o_w = (const float*)d_in[8];
    const float* gate_w = (const float*)d_in[9];
    const float* up_w = (const float*)d_in[10];
    const float* down_w = (const float*)d_in[11];
    float* out = (float*)d_out;

    void* p;
    cudaGetSymbolAddress(&p, g_xn);   float* xn = (float*)p;
    cudaGetSymbolAddress(&p, g_q);    float* q = (float*)p;
    cudaGetSymbolAddress(&p, g_k);    float* k = (float*)p;
    cudaGetSymbolAddress(&p, g_v);    float* v = (float*)p;
    cudaGetSymbolAddress(&p, g_attn); float* attn = (float*)p;
    cudaGetSymbolAddress(&p, g_h);    float* h = (float*)p;
    cudaGetSymbolAddress(&p, g_hn);   float* hn = (float*)p;
    cudaGetSymbolAddress(&p, g_act);  float* act = (float*)p;
    cudaGetSymbolAddress(&p, g_up);   float* up = (float*)p;

    cudaFuncSetAttribute(attn_kernel, cudaFuncAttributeMaxDynamicSharedMemorySize,
                         ATTN_SMEM_FLOATS * (int)sizeof(float));
    cudaFuncSetAttribute(wmma_gemm, cudaFuncAttributeMaxDynamicSharedMemorySize,
                         GEMM_SMEM_BYTES);

    dim3 blk(256);
    const int smg = GEMM_SMEM_BYTES;

    // 1. ln1
    rmsnorm_kernel<<<TOK, blk>>>(hidden, ln1, xn);
    // 2-4. q/k/v projections (tensor core)
    wmma_gemm<<<dim3((NH * HD) / GBN, TOK / GBM), blk, smg>>>(xn, q_w, q, (const float*)0, TOK, NH * HD, DIM, 0, 0, 0);
    wmma_gemm<<<dim3((NKVH * HD) / GBN, TOK / GBM), blk, smg>>>(xn, k_w, k, (const float*)0, TOK, NKVH * HD, DIM, 0, 0, 0);
    wmma_gemm<<<dim3((NKVH * HD) / GBN, TOK / GBM), blk, smg>>>(xn, v_w, v, (const float*)0, TOK, NKVH * HD, DIM, 0, 0, 0);
    // 5. RoPE
    rope_kernel<<<(TOK * NH * 64 + 255) / 256, blk>>>(q, NH);
    rope_kernel<<<(TOK * NKVH * 64 + 255) / 256, blk>>>(k, NKVH);
    // 6. attention
    attn_kernel<<<dim3(SEQ / 64, NH, BATCH), blk,
                  ATTN_SMEM_FLOATS * sizeof(float)>>>(q, k, v, attn);
    // 7. o-proj + residual
    wmma_gemm<<<dim3(DIM / GBN, TOK / GBM), blk, smg>>>(attn, o_w, h, hidden, TOK, DIM, NH * HD, 0, 0, 0);
    // 8. ln2
    rmsnorm_kernel<<<TOK, blk>>>(h, ln2, hn);
    // 9. MoD compaction
    compact_kernel<<<1, blk>>>(mask, tscore);
    // 10-11. gathered gate/up (tensor core, dynamic M)
    wmma_gemm<<<dim3(FF / GBN, TOK / GBM), blk, smg>>>(hn, gate_w, act, (const float*)0, TOK, FF, DIM, 1, 0, 1);
    wmma_gemm<<<dim3(FF / GBN, TOK / GBM), blk, smg>>>(hn, up_w, up, (const float*)0, TOK, FF, DIM, 1, 0, 1);
    // 12. silu * up
    silu_mul_kernel<<<2048, blk>>>(act, up);
    // 13. out = h
    copy_kernel<<<(TOK * DIM / 4 + 255) / 256, blk>>>(out, h);
    // 14. down-proj, scatter-add with per-token MoD scale
    wmma_gemm<<<dim3(DIM / GBN, TOK / GBM), blk, smg>>>(act, down_w, out, (const float*)0, TOK, DIM, FF, 0, 1, 1);
}

// round 6
// speedup vs baseline: 1.7832x; 1.1206x over previous
#include <cuda_runtime.h>
#include <cuda_bf16.h>
#include <cuda_pipeline.h>
#include <mma.h>
#include <stdint.h>
#include <math.h>

using namespace nvcuda;

#define TOK 4096
#define DIM 2048
#define NH 16
#define NKVH 4
#define HD 128
#define FF 7168
#define SEQ 2048
#define BATCH 2

#define GBM 128
#define GBN 128
#define GBK 32
#define GLD 40
#define STAGE_ELEMS (GBM * GLD)                 // per tile (padded)
#define STAGE_BYTES (4 * STAGE_ELEMS * 2)       // 4 tiles of bf16
#define GEMM_SMEM_BYTES (2 * STAGE_BYTES)       // 2 stages (81920) >= C tile 69632

// ---------------- scratch (static device globals; no allocation allowed) ---
__device__ float g_q[TOK * NH * HD];
__device__ float g_k[TOK * NKVH * HD];
__device__ float g_v[TOK * NKVH * HD];
__device__ float g_h[TOK * DIM];
__device__ float g_gate[TOK * FF];
__device__ float g_up[TOK * FF];
__device__ int   g_idx[TOK];
__device__ float g_scale[TOK];
__device__ int   g_nsel;

// bf16 hi/lo planes (activations)
__device__ __nv_bfloat16 g_xnh[TOK * DIM],  g_xnl[TOK * DIM];
__device__ __nv_bfloat16 g_ah[TOK * DIM],   g_al[TOK * DIM];
__device__ __nv_bfloat16 g_hnh[TOK * DIM],  g_hnl[TOK * DIM];
__device__ __nv_bfloat16 g_acth[TOK * FF],  g_actl[TOK * FF];
// bf16 hi/lo planes (weights)
__device__ __nv_bfloat16 g_qwh[DIM * DIM],  g_qwl[DIM * DIM];
__device__ __nv_bfloat16 g_kwh[NKVH * HD * DIM], g_kwl[NKVH * HD * DIM];
__device__ __nv_bfloat16 g_vwh[NKVH * HD * DIM], g_vwl[NKVH * HD * DIM];
__device__ __nv_bfloat16 g_owh[DIM * DIM],  g_owl[DIM * DIM];
__device__ __nv_bfloat16 g_gwh[FF * DIM],   g_gwl[FF * DIM];
__device__ __nv_bfloat16 g_uwh[FF * DIM],   g_uwl[FF * DIM];
__device__ __nv_bfloat16 g_dwh[DIM * FF],   g_dwl[DIM * FF];

// ---------------- fp32 -> bf16 hi/lo split --------------------------------
__device__ __forceinline__ void dsplit(float v, __nv_bfloat16& hi, __nv_bfloat16& lo) {
    hi = __float2bfloat16(v);
    lo = __float2bfloat16(v - __bfloat162float(hi));
}

// ---------------- weight / tensor split kernel -----------------------------
__global__ void split_kernel(const float* __restrict__ src,
                             __nv_bfloat16* __restrict__ hi,
                             __nv_bfloat16* __restrict__ lo, int n4) {
    int i = blockIdx.x * blockDim.x + threadIdx.x;
    if (i >= n4) return;
    float4 v = ((const float4*)src)[i];
    __nv_bfloat16 h0, l0, h1, l1, h2, l2, h3, l3;
    dsplit(v.x, h0, l0); dsplit(v.y, h1, l1);
    dsplit(v.z, h2, l2); dsplit(v.w, h3, l3);
    __nv_bfloat162* hp = (__nv_bfloat162*)hi + i * 2;
    __nv_bfloat162* lp = (__nv_bfloat162*)lo + i * 2;
    hp[0] = __nv_bfloat162(h0, h1); hp[1] = __nv_bfloat162(h2, h3);
    lp[0] = __nv_bfloat162(l0, l1); lp[1] = __nv_bfloat162(l2, l3);
}

// ---------------- bf16 split-GEMM: C[M,N] = A[M,K] @ W[N,K]^T --------------
// A, W given as pre-split hi/lo bf16 planes. 3-pass (hh + hl + lh), fp32 acc.
// cp.async double-buffered staging. gather/scatter/dynm as before.
__global__ __launch_bounds__(256)
void bf16_gemm(const __nv_bfloat16* __restrict__ Ah, const __nv_bfloat16* __restrict__ Al,
               const __nv_bfloat16* __restrict__ Wh, const __nv_bfloat16* __restrict__ Wl,
               float* __restrict__ C, const float* __restrict__ Res,
               int M, int N, int K, int gather, int scatter, int dynm) {
    const int Mreal = dynm ? g_nsel : M;
    const int bm = blockIdx.y * GBM;
    if (bm >= Mreal) return;
    const int bn = blockIdx.x * GBN;

    extern __shared__ char smraw[];

    const int tid = threadIdx.x;
    const int warp = tid >> 5;
    const int wm = (warp >> 1) * 32;     // 4 warps along M
    const int wn = (warp & 1) * 64;      // 2 warps along N

    // loader mapping: 512 16B-chunks per plane; 2 per thread (t=0,1)
    const int cc = tid & 3;              // 16B chunk within row (8 bf16)
    int lrow[2], arowg[2], wrowg[2];
    bool avalid[2];
    for (int t = 0; t < 2; t++) {
        int row = (tid >> 2) + t * 64;   // 0..127
        lrow[t] = row;
        int am = bm + row;
        avalid[t] = (am < Mreal);
        arowg[t] = avalid[t] ? (gather ? g_idx[am] : am) : 0;
        wrowg[t] = bn + row;
    }

    wmma::fragment<wmma::accumulator, 16, 16, 16, float> acc[2][4];
    for (int mt = 0; mt < 2; mt++)
        for (int nt = 0; nt < 4; nt++)
            wmma::fill_fragment(acc[mt][nt], 0.0f);

    const int nchunks = K / GBK;
    const uint4 zz = make_uint4(0u, 0u, 0u, 0u);

    // ---- stage loader ----
    // stage s base: smraw + (s&1)*STAGE_BYTES; tiles: Ahi, Alo, Whi, Wlo
    for (int c = 0; c < nchunks + 1; c++) {
        if (c < nchunks) {
            char* sb = smraw + (c & 1) * STAGE_BYTES;
            __nv_bfloat16* sAh = (__nv_bfloat16*)sb;
            __nv_bfloat16* sAl = sAh + STAGE_ELEMS;
            __nv_bfloat16* sWh = sAl + STAGE_ELEMS;
            __nv_bfloat16* sWl = sWh + STAGE_ELEMS;
            int k0 = c * GBK;
            for (int t = 0; t < 2; t++) {
                int so = lrow[t] * GLD + cc * 8;
                if (avalid[t]) {
                    size_t go = (size_t)arowg[t] * K + k0 + cc * 8;
                    __pipeline_memcpy_async(sAh + so, Ah + go, 16);
                    __pipeline_memcpy_async(sAl + so, Al + go, 16);
                } else {
                    *(uint4*)(sAh + so) = zz;
                    *(uint4*)(sAl + so) = zz;
                }
                size_t wo = (size_t)wrowg[t] * K + k0 + cc * 8;
                __pipeline_memcpy_async(sWh + so, Wh + wo, 16);
                __pipeline_memcpy_async(sWl + so, Wl + wo, 16);
            }
            __pipeline_commit();
        }
        if (c > 0) {
            // compute on stage c-1
            __pipeline_wait_prior(c < nchunks ? 1 : 0);
            __syncthreads();
            char* sb = smraw + ((c - 1) & 1) * STAGE_BYTES;
            const __nv_bfloat16* sAh = (const __nv_bfloat16*)sb;
            const __nv_bfloat16* sAl = sAh + STAGE_ELEMS;
            const __nv_bfloat16* sWh = sAl + STAGE_ELEMS;
            const __nv_bfloat16* sWl = sWh + STAGE_ELEMS;
            for (int kc = 0; kc < GBK; kc += 16) {
                wmma::fragment<wmma::matrix_a, 16, 16, 16, __nv_bfloat16, wmma::row_major> ah[2], al[2];
                wmma::fragment<wmma::matrix_b, 16, 16, 16, __nv_bfloat16, wmma::col_major> bh[4], bl[4];
                for (int mt = 0; mt < 2; mt++) {
                    wmma::load_matrix_sync(ah[mt], sAh + (wm + mt * 16) * GLD + kc, GLD);
                    wmma::load_matrix_sync(al[mt], sAl + (wm + mt * 16) * GLD + kc, GLD);
                }
                for (int nt = 0; nt < 4; nt++) {
                    wmma::load_matrix_sync(bh[nt], sWh + (wn + nt * 16) * GLD + kc, GLD);
                    wmma::load_matrix_sync(bl[nt], sWl + (wn + nt * 16) * GLD + kc, GLD);
                }
                for (int mt = 0; mt < 2; mt++)
                    for (int nt = 0; nt < 4; nt++) {
                        wmma::mma_sync(acc[mt][nt], ah[mt], bh[nt], acc[mt][nt]);
                        wmma::mma_sync(acc[mt][nt], ah[mt], bl[nt], acc[mt][nt]);
                        wmma::mma_sync(acc[mt][nt], al[mt], bh[nt], acc[mt][nt]);
                    }
            }
            __syncthreads();
        }
    }

    // ---- epilogue through smem C tile (reuses pipeline smem) ----
    float* Cs = (float*)smraw;     // 128 x 136
    for (int mt = 0; mt < 2; mt++)
        for (int nt = 0; nt < 4; nt++)
            wmma::store_matrix_sync(Cs + (wm + mt * 16) * 136 + wn + nt * 16,
                                    acc[mt][nt], 136, wmma::mem_row_major);
    __syncthreads();

    {
        int r = tid >> 1;
        int c0 = (tid & 1) * 64;
        int row = bm + r;
        if (row < Mreal) {
            int crow = scatter ? g_idx[row] : row;
            const float* cr = Cs + r * 136 + c0;
            size_t off = (size_t)crow * N + bn + c0;
            if (scatter) {
                float rs = g_scale[crow];
                for (int j = 0; j < 64; j++) C[off + j] += rs * cr[j];
            } else if (Res) {
                for (int j = 0; j < 64; j++) C[off + j] = Res[off + j] + cr[j];
            } else {
                for (int j = 0; j < 64; j++) C[off + j] = cr[j];
            }
        }
    }
}

// ---------------- RMSNorm (writes split bf16 planes) -----------------------
__global__ void rmsnorm_split_kernel(const float* __restrict__ x,
                                     const float* __restrict__ w,
                                     __nv_bfloat16* __restrict__ oh,
                                     __nv_bfloat16* __restrict__ ol) {
    const int row = blockIdx.x;
    const float* xr = x + (size_t)row * DIM;
    float ss = 0.f;
    for (int i = threadIdx.x; i < DIM; i += 256) {
        float v = xr[i];
        ss += v * v;
    }
    __shared__ float red[256];
    red[threadIdx.x] = ss;
    __syncthreads();
    for (int off = 128; off > 0; off >>= 1) {
        if (threadIdx.x < off) red[threadIdx.x] += red[threadIdx.x + off];
        __syncthreads();
    }
    float rs = rsqrtf(red[0] / (float)DIM + 1e-5f);
    for (int i = threadIdx.x; i < DIM; i += 256) {
        float v = xr[i] * rs * w[i];
        __nv_bfloat16 hi, lo;
        dsplit(v, hi, lo);
        oh[(size_t)row * DIM + i] = hi;
        ol[(size_t)row * DIM + i] = lo;
    }
}

// ---------------- RoPE ----------------------------------------------------
__global__ void rope_kernel(float* __restrict__ x, int nHeads) {
    int i = blockIdx.x * blockDim.x + threadIdx.x;
    int total = TOK * nHeads * 64;
    if (i >= total) return;
    int half = i & 63;
    int t = i >> 6;
    int hd = t % nHeads;
    int tok = t / nHeads;
    int pos = tok % SEQ;
    float inv = expf(-logf(10000.f) * (float)half * (1.f / 64.f));
    float ang = (float)pos * inv;
    float c = cosf(ang), s = sinf(ang);
    float* base = x + (size_t)tok * (nHeads * HD) + hd * HD + half;
    float x1 = base[0], x2 = base[64];
    base[0] = x1 * c - x2 * s;
    base[64] = x2 * c + x1 * s;
}

// ---------------- Flash attention (fp32, causal, GQA) ---------------------
// Output written directly as split bf16 planes (consumed only by o-proj).
#define ATTN_SMEM_FLOATS (128 * 65 * 2 + 64 * 128 + 64 * 65 + 64 * 3)

__global__ void attn_kernel(const float* __restrict__ Qm,
                            const float* __restrict__ Km,
                            const float* __restrict__ Vm,
                            __nv_bfloat16* __restrict__ Oh,
                            __nv_bfloat16* __restrict__ Ol) {
    extern __shared__ float sm[];
    float* Qs = sm;                 // [128][65] transposed
    float* Ks = Qs + 128 * 65;      // [128][65] transposed
    float* Vs = Ks + 128 * 65;      // [64][128]
    float* Ps = Vs + 64 * 128;      // [64][65]
    float* rowm = Ps + 64 * 65;
    float* rowl = rowm + 64;
    float* rowsc = rowl + 64;

    const int tid = threadIdx.x;
    const int qt = blockIdx.x, h = blockIdx.y, b = blockIdx.z;
    const int kvh = h / (NH / NKVH);
    const int q0 = qt * 64;

    for (int i = tid; i < 64 * 128; i += 256) {
        int r = i >> 7, d = i & 127;
        Qs[d * 65 + r] = Qm[((size_t)(b * SEQ + q0 + r)) * (NH * HD) + h * HD + d];
    }
    if (tid < 64) { rowm[tid] = -1e30f; rowl[tid] = 0.f; }

    float Oacc[32];
#pragma unroll
    for (int j = 0; j < 32; j++) Oacc[j] = 0.f;

    const int rc = tid >> 2;
    const int cg = tid & 3;
    const int tx = tid & 15, ty = tid >> 4;

    for (int kt = 0; kt <= qt; kt++) {
        __syncthreads();
        for (int i = tid; i < 64 * 128; i += 256) {
            int c = i >> 7, d = i & 127;
            size_t off = ((size_t)(b * SEQ + kt * 64 + c)) * (NKVH * HD) + kvh * HD + d;
            Ks[d * 65 + c] = Km[off];
            Vs[c * 128 + d] = Vm[off];
        }
        __syncthreads();

        float sacc[4][4];
#pragma unroll
        for (int i = 0; i < 4; i++)
#pragma unroll
            for (int j = 0; j < 4; j++) sacc[i][j] = 0.f;

        for (int kd = 0; kd < 128; kd++) {
            float ra[4], rb[4];
#pragma unroll
            for (int i = 0; i < 4; i++) ra[i] = Qs[kd * 65 + ty * 4 + i];
#pragma unroll
            for (int j = 0; j < 4; j++) rb[j] = Ks[kd * 65 + tx * 4 + j];
#pragma unroll
            for (int i = 0; i < 4; i++)
#pragma unroll
                for (int j = 0; j < 4; j++)
                    sacc[i][j] = fmaf(ra[i], rb[j], sacc[i][j]);
        }
        const float qk_scale = 0.08838834764831845f;
#pragma unroll
        for (int i = 0; i < 4; i++) {
            int gq = q0 + ty * 4 + i;
#pragma unroll
            for (int j = 0; j < 4; j++) {
                int gk = kt * 64 + tx * 4 + j;
                float v = sacc[i][j] * qk_scale;
                if (gk > gq) v = -1e30f;
                Ps[(ty * 4 + i) * 65 + tx * 4 + j] = v;
            }
        }
        __syncthreads();

        if (tid < 64) {
            int r = tid;
            float m0 = rowm[r];
            float mx = m0;
            for (int c = 0; c < 64; c++) mx = fmaxf(mx, Ps[r * 65 + c]);
            float sc = __expf(m0 - mx);
            float sum = 0.f;
            for (int c = 0; c < 64; c++) {
                float p = __expf(Ps[r * 65 + c] - mx);
                Ps[r * 65 + c] = p;
                sum += p;
            }
            rowl[r] = rowl[r] * sc + sum;
            rowm[r] = mx;
            rowsc[r] = sc;
        }
        __syncthreads();

        float sc = rowsc[rc];
#pragma unroll
        for (int j = 0; j < 32; j++) Oacc[j] *= sc;
        for (int kk = 0; kk < 64; kk++) {
            float p = Ps[rc * 65 + kk];
#pragma unroll
            for (int j = 0; j < 32; j++)
                Oacc[j] = fmaf(p, Vs[kk * 128 + cg + 4 * j], Oacc[j]);
        }
    }
    __syncthreads();
    float linv = 1.f / rowl[rc];
    size_t obase = ((size_t)(b * SEQ + q0 + rc)) * (NH * HD) + h * HD + cg;
#pragma unroll
    for (int j = 0; j < 32; j++) {
        __nv_bfloat16 hi, lo;
        dsplit(Oacc[j] * linv, hi, lo);
        Oh[obase + 4 * j] = hi;
        Ol[obase + 4 * j] = lo;
    }
}

// ---------------- MoD compaction (single block, deterministic) ------------
__global__ void compact_kernel(const int* __restrict__ mask,
                               const float* __restrict__ scores) {
    __shared__ int ssum[256];
    __shared__ int base;
    const int t = threadIdx.x;
    if (t == 0) base = 0;
    __syncthreads();
    for (int start = 0; start < TOK; start += 256) {
        int i = start + t;
        int f = (mask[i] != 0) ? 1 : 0;
        g_scale[i] = 0.5f + (scores[i] - 0.5f) * 0.7f;
        ssum[t] = f;
        __syncthreads();
        for (int off = 1; off < 256; off <<= 1) {
            int v = (t >= off) ? ssum[t - off] : 0;
            __syncthreads();
            ssum[t] += v;
            __syncthreads();
        }
        if (f) g_idx[base + ssum[t] - 1] = i;
        __syncthreads();
        if (t == 0) base += ssum[255];
        __syncthreads();
    }
    if (t == 0) g_nsel = base;
}

// ---------------- SiLU(gate) * up -> split bf16 act (dynamic rows) --------
__global__ void silu_mul_kernel(const float* __restrict__ gate,
                                const float* __restrict__ up,
                                __nv_bfloat16* __restrict__ acth,
                                __nv_bfloat16* __restrict__ actl) {
    size_t total = (size_t)g_nsel * FF;
    size_t stride = (size_t)gridDim.x * blockDim.x;
    for (size_t i = (size_t)blockIdx.x * blockDim.x + threadIdx.x; i < total; i += stride) {
        float g = gate[i];
        float v = (g / (1.f + __expf(-g))) * up[i];
        __nv_bfloat16 hi, lo;
        dsplit(v, hi, lo);
        acth[i] = hi;
        actl[i] = lo;
    }
}

// ---------------- residual copy to output ---------------------------------
__global__ void copy_kernel(float* __restrict__ dst, const float* __restrict__ src) {
    int i = blockIdx.x * blockDim.x + threadIdx.x;
    if (i < TOK * DIM / 4)
        ((float4*)dst)[i] = ((const float4*)src)[i];
}

// ---------------- driver ---------------------------------------------------
extern "C" void kernel_launch(void* const* d_in, const int* in_sizes, int n_in,
                              void* d_out, int out_size) {
    const float* hidden = (const float*)d_in[0];
    const int* mask = (const int*)d_in[1];
    const float* tscore = (const float*)d_in[2];
    const float* ln1 = (const float*)d_in[3];
    const float* ln2 = (const float*)d_in[4];
    const float* q_w = (const float*)d_in[5];
    const float* k_w = (const float*)d_in[6];
    const float* v_w = (const float*)d_in[7];
    const float* o_w = (const float*)d_in[8];
    const float* gate_w = (const float*)d_in[9];
    const float* up_w = (const float*)d_in[10];
    const float* down_w = (const float*)d_in[11];
    float* out = (float*)d_out;

    void* p;
    cudaGetSymbolAddress(&p, g_q);    float* q = (float*)p;
    cudaGetSymbolAddress(&p, g_k);    float* k = (float*)p;
    cudaGetSymbolAddress(&p, g_v);    float* v = (float*)p;
    cudaGetSymbolAddress(&p, g_h);    float* h = (float*)p;
    cudaGetSymbolAddress(&p, g_gate); float* gate = (float*)p;
    cudaGetSymbolAddress(&p, g_up);   float* up = (float*)p;

    __nv_bfloat16 *xnh, *xnl, *ah, *al, *hnh, *hnl, *acth, *actl;
    __nv_bfloat16 *qwh, *qwl, *kwh, *kwl, *vwh, *vwl, *owh, *owl;
    __nv_bfloat16 *gwh, *gwl, *uwh, *uwl, *dwh, *dwl;
    cudaGetSymbolAddress(&p, g_xnh);  xnh = (__nv_bfloat16*)p;
    cudaGetSymbolAddress(&p, g_xnl);  xnl = (__nv_bfloat16*)p;
    cudaGetSymbolAddress(&p, g_ah);   ah = (__nv_bfloat16*)p;
    cudaGetSymbolAddress(&p, g_al);   al = (__nv_bfloat16*)p;
    cudaGetSymbolAddress(&p, g_hnh);  hnh = (__nv_bfloat16*)p;
    cudaGetSymbolAddress(&p, g_hnl);  hnl = (__nv_bfloat16*)p;
    cudaGetSymbolAddress(&p, g_acth); acth = (__nv_bfloat16*)p;
    cudaGetSymbolAddress(&p, g_actl); actl = (__nv_bfloat16*)p;
    cudaGetSymbolAddress(&p, g_qwh);  qwh = (__nv_bfloat16*)p;
    cudaGetSymbolAddress(&p, g_qwl);  qwl = (__nv_bfloat16*)p;
    cudaGetSymbolAddress(&p, g_kwh);  kwh = (__nv_bfloat16*)p;
    cudaGetSymbolAddress(&p, g_kwl);  kwl = (__nv_bfloat16*)p;
    cudaGetSymbolAddress(&p, g_vwh);  vwh = (__nv_bfloat16*)p;
    cudaGetSymbolAddress(&p, g_vwl);  vwl = (__nv_bfloat16*)p;
    cudaGetSymbolAddress(&p, g_owh);  owh = (__nv_bfloat16*)p;
    cudaGetSymbolAddress(&p, g_owl);  owl = (__nv_bfloat16*)p;
    cudaGetSymbolAddress(&p, g_gwh);  gwh = (__nv_bfloat16*)p;
    cudaGetSymbolAddress(&p, g_gwl);  gwl = (__nv_bfloat16*)p;
    cudaGetSymbolAddress(&p, g_uwh);  uwh = (__nv_bfloat16*)p;
    cudaGetSymbolAddress(&p, g_uwl);  uwl = (__nv_bfloat16*)p;
    cudaGetSymbolAddress(&p, g_dwh);  dwh = (__nv_bfloat16*)p;
    cudaGetSymbolAddress(&p, g_dwl);  dwl = (__nv_bfloat16*)p;

    cudaFuncSetAttribute(attn_kernel, cudaFuncAttributeMaxDynamicSharedMemorySize,
                         ATTN_SMEM_FLOATS * (int)sizeof(float));
    cudaFuncSetAttribute(bf16_gemm, cudaFuncAttributeMaxDynamicSharedMemorySize,
                         GEMM_SMEM_BYTES);

    dim3 blk(256);
    const int smg = GEMM_SMEM_BYTES;

    // 0. split weights to bf16 hi/lo planes
    split_kernel<<<(DIM * DIM / 4 + 255) / 256, blk>>>(q_w, qwh, qwl, DIM * DIM / 4);
    split_kernel<<<(NKVH * HD * DIM / 4 + 255) / 256, blk>>>(k_w, kwh, kwl, NKVH * HD * DIM / 4);
    split_kernel<<<(NKVH * HD * DIM / 4 + 255) / 256, blk>>>(v_w, vwh, vwl, NKVH * HD * DIM / 4);
    split_kernel<<<(DIM * DIM / 4 + 255) / 256, blk>>>(o_w, owh, owl, DIM * DIM / 4);
    split_kernel<<<(FF * DIM / 4 + 255) / 256, blk>>>(gate_w, gwh, gwl, FF * DIM / 4);
    split_kernel<<<(FF * DIM / 4 + 255) / 256, blk>>>(up_w, uwh, uwl, FF * DIM / 4);
    split_kernel<<<(DIM * FF / 4 + 255) / 256, blk>>>(down_w, dwh, dwl, DIM * FF / 4);

    // 1. ln1 -> split planes
    rmsnorm_split_kernel<<<TOK, blk>>>(hidden, ln1, xnh, xnl);
    // 2-4. q/k/v projections
    bf16_gemm<<<dim3((NH * HD) / GBN, TOK / GBM), blk, smg>>>(xnh, xnl, qwh, qwl, q, (const float*)0, TOK, NH * HD, DIM, 0, 0, 0);
    bf16_gemm<<<dim3((NKVH * HD) / GBN, TOK / GBM), blk, smg>>>(xnh, xnl, kwh, kwl, k, (const float*)0, TOK, NKVH * HD, DIM, 0, 0, 0);
    bf16_gemm<<<dim3((NKVH * HD) / GBN, TOK / GBM), blk, smg>>>(xnh, xnl, vwh, vwl, v, (const float*)0, TOK, NKVH * HD, DIM, 0, 0, 0);
    // 5. RoPE
    rope_kernel<<<(TOK * NH * 64 + 255) / 256, blk>>>(q, NH);
    rope_kernel<<<(TOK * NKVH * 64 + 255) / 256, blk>>>(k, NKVH);
    // 6. attention -> split planes
    attn_kernel<<<dim3(SEQ / 64, NH, BATCH), blk,
                  ATTN_SMEM_FLOATS * sizeof(float)>>>(q, k, v, ah, al);
    // 7. o-proj + residual
    bf16_gemm<<<dim3(DIM / GBN, TOK / GBM), blk, smg>>>(ah, al, owh, owl, h, hidden, TOK, DIM, NH * HD, 0, 0, 0);
    // 8. ln2 -> split planes
    rmsnorm_split_kernel<<<TOK, blk>>>(h, ln2, hnh, hnl);
    // 9. MoD compaction
    compact_kernel<<<1, blk>>>(mask, tscore);
    // 10-11. gathered gate/up (dynamic M)
    bf16_gemm<<<dim3(FF / GBN, TOK / GBM), blk, smg>>>(hnh, hnl, gwh, gwl, gate, (const float*)0, TOK, FF, DIM, 1, 0, 1);
    bf16_gemm<<<dim3(FF / GBN, TOK / GBM), blk, smg>>>(hnh, hnl, uwh, uwl, up, (const float*)0, TOK, FF, DIM, 1, 0, 1);
    // 12. silu * up -> split act planes
    silu_mul_kernel<<<2048, blk>>>(gate, up, acth, actl);
    // 13. out = h
    copy_kernel<<<(TOK * DIM / 4 + 255) / 256, blk>>>(out, h);
    // 14. down-proj, scatter-add with per-token MoD scale
    bf16_gemm<<<dim3(DIM / GBN, TOK / GBM), blk, smg>>>(acth, actl, dwh, dwl, out, (const float*)0, TOK, DIM, FF, 0, 1, 1);
}

// round 7
// speedup vs baseline: 2.7504x; 1.5424x over previous
#include <cuda_runtime.h>
#include <cuda_fp16.h>
#include <cuda_pipeline.h>
#include <mma.h>
#include <stdint.h>
#include <math.h>

using namespace nvcuda;

#define TOK 4096
#define DIM 2048
#define NH 16
#define NKVH 4
#define HD 128
#define FF 7168
#define SEQ 2048
#define BATCH 2

#define GBM 128
#define GBN 128
#define GBK 64
#define GLD 72
#define TILE_ELEMS (GBM * GLD)                   // padded halfs per tile
#define STAGE_BYTES (2 * TILE_ELEMS * 2)         // A + W tiles, fp16
#define GEMM_SMEM_BYTES (2 * STAGE_BYTES)        // 73728 >= C tile 69632

// ---------------- scratch (static device globals; no allocation allowed) ---
__device__ float g_q[TOK * NH * HD];
__device__ float g_k[TOK * NKVH * HD];
__device__ float g_v[TOK * NKVH * HD];
__device__ float g_h[TOK * DIM];
__device__ float g_gate[TOK * FF];
__device__ float g_up[TOK * FF];
__device__ int   g_idx[TOK];
__device__ float g_scale[TOK];
__device__ int   g_nsel;

// fp16 planes (activations)
__device__ __half g_xnh[TOK * DIM];
__device__ __half g_ah[TOK * DIM];
__device__ __half g_hnh[TOK * DIM];
__device__ __half g_acth[TOK * FF];
// fp16 planes (weights)
__device__ __half g_qwh[DIM * DIM];
__device__ __half g_kwh[NKVH * HD * DIM];
__device__ __half g_vwh[NKVH * HD * DIM];
__device__ __half g_owh[DIM * DIM];
__device__ __half g_gwh[FF * DIM];
__device__ __half g_uwh[FF * DIM];
__device__ __half g_dwh[DIM * FF];

// ---------------- fp32 -> fp16 convert kernel ------------------------------
__global__ void cvt_kernel(const float* __restrict__ src,
                           __half* __restrict__ dst, int n4) {
    int i = blockIdx.x * blockDim.x + threadIdx.x;
    if (i >= n4) return;
    float4 v = ((const float4*)src)[i];
    __half2* hp = (__half2*)dst + i * 2;
    hp[0] = __floats2half2_rn(v.x, v.y);
    hp[1] = __floats2half2_rn(v.z, v.w);
}

// ---------------- fp16 GEMM: C[M,N] = A[M,K] @ W[N,K]^T --------------------
// Single-pass fp16 operands, fp32 accumulate. cp.async double-buffered.
// gather: A row = g_idx[row]; scatter: C row = g_idx[row], C += scale*acc;
// dynm: effective M = g_nsel.
__global__ __launch_bounds__(256)
void fp16_gemm(const __half* __restrict__ Ah, const __half* __restrict__ Wh,
               float* __restrict__ C, const float* __restrict__ Res,
               int M, int N, int K, int gather, int scatter, int dynm) {
    const int Mreal = dynm ? g_nsel : M;
    const int bm = blockIdx.y * GBM;
    if (bm >= Mreal) return;
    const int bn = blockIdx.x * GBN;

    extern __shared__ char smraw[];

    const int tid = threadIdx.x;
    const int warp = tid >> 5;
    const int wm = (warp >> 1) * 32;     // 4 warps along M
    const int wn = (warp & 1) * 64;      // 2 warps along N

    // loader mapping: GBK=64 halfs/row = 8 chunks of 16B; 128 rows/tile.
    const int cc = tid & 7;              // chunk within row
    int lrow[4], arowg[4], wrowg[4];
    bool avalid[4];
    for (int t = 0; t < 4; t++) {
        int row = (tid >> 3) + t * 32;   // 0..127
        lrow[t] = row;
        int am = bm + row;
        avalid[t] = (am < Mreal);
        arowg[t] = avalid[t] ? (gather ? g_idx[am] : am) : 0;
        wrowg[t] = bn + row;
    }

    wmma::fragment<wmma::accumulator, 16, 16, 16, float> acc[2][4];
    for (int mt = 0; mt < 2; mt++)
        for (int nt = 0; nt < 4; nt++)
            wmma::fill_fragment(acc[mt][nt], 0.0f);

    const int nchunks = K / GBK;
    const uint4 zz = make_uint4(0u, 0u, 0u, 0u);

    for (int c = 0; c < nchunks + 1; c++) {
        if (c < nchunks) {
            char* sb = smraw + (c & 1) * STAGE_BYTES;
            __half* sA = (__half*)sb;
            __half* sW = sA + TILE_ELEMS;
            int k0 = c * GBK;
            for (int t = 0; t < 4; t++) {
                int so = lrow[t] * GLD + cc * 8;
                if (avalid[t]) {
                    size_t go = (size_t)arowg[t] * K + k0 + cc * 8;
                    __pipeline_memcpy_async(sA + so, Ah + go, 16);
                } else {
                    *(uint4*)(sA + so) = zz;
                }
                size_t wo = (size_t)wrowg[t] * K + k0 + cc * 8;
                __pipeline_memcpy_async(sW + so, Wh + wo, 16);
            }
            __pipeline_commit();
        }
        if (c > 0) {
            __pipeline_wait_prior(c < nchunks ? 1 : 0);
            __syncthreads();
            char* sb = smraw + ((c - 1) & 1) * STAGE_BYTES;
            const __half* sA = (const __half*)sb;
            const __half* sW = sA + TILE_ELEMS;
            for (int kc = 0; kc < GBK; kc += 16) {
                wmma::fragment<wmma::matrix_a, 16, 16, 16, __half, wmma::row_major> af[2];
                wmma::fragment<wmma::matrix_b, 16, 16, 16, __half, wmma::col_major> bf[4];
                for (int mt = 0; mt < 2; mt++)
                    wmma::load_matrix_sync(af[mt], sA + (wm + mt * 16) * GLD + kc, GLD);
                for (int nt = 0; nt < 4; nt++)
                    wmma::load_matrix_sync(bf[nt], sW + (wn + nt * 16) * GLD + kc, GLD);
                for (int mt = 0; mt < 2; mt++)
                    for (int nt = 0; nt < 4; nt++)
                        wmma::mma_sync(acc[mt][nt], af[mt], bf[nt], acc[mt][nt]);
            }
            __syncthreads();
        }
    }

    // ---- epilogue through smem C tile (reuses pipeline smem) ----
    float* Cs = (float*)smraw;     // 128 x 136
    for (int mt = 0; mt < 2; mt++)
        for (int nt = 0; nt < 4; nt++)
            wmma::store_matrix_sync(Cs + (wm + mt * 16) * 136 + wn + nt * 16,
                                    acc[mt][nt], 136, wmma::mem_row_major);
    __syncthreads();

    {
        int r = tid >> 1;
        int c0 = (tid & 1) * 64;
        int row = bm + r;
        if (row < Mreal) {
            int crow = scatter ? g_idx[row] : row;
            const float* cr = Cs + r * 136 + c0;
            size_t off = (size_t)crow * N + bn + c0;
            if (scatter) {
                float rs = g_scale[crow];
                for (int j = 0; j < 64; j++) C[off + j] += rs * cr[j];
            } else if (Res) {
                for (int j = 0; j < 64; j++) C[off + j] = Res[off + j] + cr[j];
            } else {
                for (int j = 0; j < 64; j++) C[off + j] = cr[j];
            }
        }
    }
}

// ---------------- RMSNorm (writes fp16 plane) -------------------------------
__global__ void rmsnorm_half_kernel(const float* __restrict__ x,
                                    const float* __restrict__ w,
                                    __half* __restrict__ oh) {
    const int row = blockIdx.x;
    const float* xr = x + (size_t)row * DIM;
    float ss = 0.f;
    for (int i = threadIdx.x; i < DIM; i += 256) {
        float v = xr[i];
        ss += v * v;
    }
    __shared__ float red[256];
    red[threadIdx.x] = ss;
    __syncthreads();
    for (int off = 128; off > 0; off >>= 1) {
        if (threadIdx.x < off) red[threadIdx.x] += red[threadIdx.x + off];
        __syncthreads();
    }
    float rs = rsqrtf(red[0] / (float)DIM + 1e-5f);
    for (int i = threadIdx.x; i < DIM; i += 256)
        oh[(size_t)row * DIM + i] = __float2half(xr[i] * rs * w[i]);
}

// ---------------- RoPE ----------------------------------------------------
__global__ void rope_kernel(float* __restrict__ x, int nHeads) {
    int i = blockIdx.x * blockDim.x + threadIdx.x;
    int total = TOK * nHeads * 64;
    if (i >= total) return;
    int half = i & 63;
    int t = i >> 6;
    int hd = t % nHeads;
    int tok = t / nHeads;
    int pos = tok % SEQ;
    float inv = expf(-logf(10000.f) * (float)half * (1.f / 64.f));
    float ang = (float)pos * inv;
    float c = cosf(ang), s = sinf(ang);
    float* base = x + (size_t)tok * (nHeads * HD) + hd * HD + half;
    float x1 = base[0], x2 = base[64];
    base[0] = x1 * c - x2 * s;
    base[64] = x2 * c + x1 * s;
}

// ---------------- Flash attention (fp32, causal, GQA) ---------------------
// Output written directly as fp16 plane (consumed only by o-proj).
#define ATTN_SMEM_FLOATS (128 * 65 * 2 + 64 * 128 + 64 * 65 + 64 * 3)

__global__ void attn_kernel(const float* __restrict__ Qm,
                            const float* __restrict__ Km,
                            const float* __restrict__ Vm,
                            __half* __restrict__ Oh) {
    extern __shared__ float sm[];
    float* Qs = sm;                 // [128][65] transposed
    float* Ks = Qs + 128 * 65;      // [128][65] transposed
    float* Vs = Ks + 128 * 65;      // [64][128]
    float* Ps = Vs + 64 * 128;      // [64][65]
    float* rowm = Ps + 64 * 65;
    float* rowl = rowm + 64;
    float* rowsc = rowl + 64;

    const int tid = threadIdx.x;
    const int qt = blockIdx.x, h = blockIdx.y, b = blockIdx.z;
    const int kvh = h / (NH / NKVH);
    const int q0 = qt * 64;

    for (int i = tid; i < 64 * 128; i += 256) {
        int r = i >> 7, d = i & 127;
        Qs[d * 65 + r] = Qm[((size_t)(b * SEQ + q0 + r)) * (NH * HD) + h * HD + d];
    }
    if (tid < 64) { rowm[tid] = -1e30f; rowl[tid] = 0.f; }

    float Oacc[32];
#pragma unroll
    for (int j = 0; j < 32; j++) Oacc[j] = 0.f;

    const int rc = tid >> 2;
    const int cg = tid & 3;
    const int tx = tid & 15, ty = tid >> 4;

    for (int kt = 0; kt <= qt; kt++) {
        __syncthreads();
        for (int i = tid; i < 64 * 128; i += 256) {
            int c = i >> 7, d = i & 127;
            size_t off = ((size_t)(b * SEQ + kt * 64 + c)) * (NKVH * HD) + kvh * HD + d;
            Ks[d * 65 + c] = Km[off];
            Vs[c * 128 + d] = Vm[off];
        }
        __syncthreads();

        float sacc[4][4];
#pragma unroll
        for (int i = 0; i < 4; i++)
#pragma unroll
            for (int j = 0; j < 4; j++) sacc[i][j] = 0.f;

        for (int kd = 0; kd < 128; kd++) {
            float ra[4], rb[4];
#pragma unroll
            for (int i = 0; i < 4; i++) ra[i] = Qs[kd * 65 + ty * 4 + i];
#pragma unroll
            for (int j = 0; j < 4; j++) rb[j] = Ks[kd * 65 + tx * 4 + j];
#pragma unroll
            for (int i = 0; i < 4; i++)
#pragma unroll
                for (int j = 0; j < 4; j++)
                    sacc[i][j] = fmaf(ra[i], rb[j], sacc[i][j]);
        }
        const float qk_scale = 0.08838834764831845f;
#pragma unroll
        for (int i = 0; i < 4; i++) {
            int gq = q0 + ty * 4 + i;
#pragma unroll
            for (int j = 0; j < 4; j++) {
                int gk = kt * 64 + tx * 4 + j;
                float v = sacc[i][j] * qk_scale;
                if (gk > gq) v = -1e30f;
                Ps[(ty * 4 + i) * 65 + tx * 4 + j] = v;
            }
        }
        __syncthreads();

        if (tid < 64) {
            int r = tid;
            float m0 = rowm[r];
            float mx = m0;
            for (int c = 0; c < 64; c++) mx = fmaxf(mx, Ps[r * 65 + c]);
            float sc = __expf(m0 - mx);
            float sum = 0.f;
            for (int c = 0; c < 64; c++) {
                float p = __expf(Ps[r * 65 + c] - mx);
                Ps[r * 65 + c] = p;
                sum += p;
            }
            rowl[r] = rowl[r] * sc + sum;
            rowm[r] = mx;
            rowsc[r] = sc;
        }
        __syncthreads();

        float sc = rowsc[rc];
#pragma unroll
        for (int j = 0; j < 32; j++) Oacc[j] *= sc;
        for (int kk = 0; kk < 64; kk++) {
            float p = Ps[rc * 65 + kk];
#pragma unroll
            for (int j = 0; j < 32; j++)
                Oacc[j] = fmaf(p, Vs[kk * 128 + cg + 4 * j], Oacc[j]);
        }
    }
    __syncthreads();
    float linv = 1.f / rowl[rc];
    size_t obase = ((size_t)(b * SEQ + q0 + rc)) * (NH * HD) + h * HD + cg;
#pragma unroll
    for (int j = 0; j < 32; j++)
        Oh[obase + 4 * j] = __float2half(Oacc[j] * linv);
}

// ---------------- MoD compaction (single block, deterministic) ------------
__global__ void compact_kernel(const int* __restrict__ mask,
                               const float* __restrict__ scores) {
    __shared__ int ssum[256];
    __shared__ int base;
    const int t = threadIdx.x;
    if (t == 0) base = 0;
    __syncthreads();
    for (int start = 0; start < TOK; start += 256) {
        int i = start + t;
        int f = (mask[i] != 0) ? 1 : 0;
        g_scale[i] = 0.5f + (scores[i] - 0.5f) * 0.7f;
        ssum[t] = f;
        __syncthreads();
        for (int off = 1; off < 256; off <<= 1) {
            int v = (t >= off) ? ssum[t - off] : 0;
            __syncthreads();
            ssum[t] += v;
            __syncthreads();
        }
        if (f) g_idx[base + ssum[t] - 1] = i;
        __syncthreads();
        if (t == 0) base += ssum[255];
        __syncthreads();
    }
    if (t == 0) g_nsel = base;
}

// ---------------- SiLU(gate) * up -> fp16 act (dynamic rows) --------------
__global__ void silu_mul_kernel(const float* __restrict__ gate,
                                const float* __restrict__ up,
                                __half* __restrict__ acth) {
    size_t total = (size_t)g_nsel * FF;
    size_t stride = (size_t)gridDim.x * blockDim.x;
    for (size_t i = (size_t)blockIdx.x * blockDim.x + threadIdx.x; i < total; i += stride) {
        float g = gate[i];
        acth[i] = __float2half((g / (1.f + __expf(-g))) * up[i]);
    }
}

// ---------------- residual copy to output ---------------------------------
__global__ void copy_kernel(float* __restrict__ dst, const float* __restrict__ src) {
    int i = blockIdx.x * blockDim.x + threadIdx.x;
    if (i < TOK * DIM / 4)
        ((float4*)dst)[i] = ((const float4*)src)[i];
}

// ---------------- driver ---------------------------------------------------
extern "C" void kernel_launch(void* const* d_in, const int* in_sizes, int n_in,
                              void* d_out, int out_size) {
    const float* hidden = (const float*)d_in[0];
    const int* mask = (const int*)d_in[1];
    const float* tscore = (const float*)d_in[2];
    const float* ln1 = (const float*)d_in[3];
    const float* ln2 = (const float*)d_in[4];
    const float* q_w = (const float*)d_in[5];
    const float* k_w = (const float*)d_in[6];
    const float* v_w = (const float*)d_in[7];
    const float* o_w = (const float*)d_in[8];
    const float* gate_w = (const float*)d_in[9];
    const float* up_w = (const float*)d_in[10];
    const float* down_w = (const float*)d_in[11];
    float* out = (float*)d_out;

    void* p;
    cudaGetSymbolAddress(&p, g_q);    float* q = (float*)p;
    cudaGetSymbolAddress(&p, g_k);    float* k = (float*)p;
    cudaGetSymbolAddress(&p, g_v);    float* v = (float*)p;
    cudaGetSymbolAddress(&p, g_h);    float* h = (float*)p;
    cudaGetSymbolAddress(&p, g_gate); float* gate = (float*)p;
    cudaGetSymbolAddress(&p, g_up);   float* up = (float*)p;

    __half *xnh, *ah, *hnh, *acth;
    __half *qwh, *kwh, *vwh, *owh, *gwh, *uwh, *dwh;
    cudaGetSymbolAddress(&p, g_xnh);  xnh = (__half*)p;
    cudaGetSymbolAddress(&p, g_ah);   ah = (__half*)p;
    cudaGetSymbolAddress(&p, g_hnh);  hnh = (__half*)p;
    cudaGetSymbolAddress(&p, g_acth); acth = (__half*)p;
    cudaGetSymbolAddress(&p, g_qwh);  qwh = (__half*)p;
    cudaGetSymbolAddress(&p, g_kwh);  kwh = (__half*)p;
    cudaGetSymbolAddress(&p, g_vwh);  vwh = (__half*)p;
    cudaGetSymbolAddress(&p, g_owh);  owh = (__half*)p;
    cudaGetSymbolAddress(&p, g_gwh);  gwh = (__half*)p;
    cudaGetSymbolAddress(&p, g_uwh);  uwh = (__half*)p;
    cudaGetSymbolAddress(&p, g_dwh);  dwh = (__half*)p;

    cudaFuncSetAttribute(attn_kernel, cudaFuncAttributeMaxDynamicSharedMemorySize,
                         ATTN_SMEM_FLOATS * (int)sizeof(float));
    cudaFuncSetAttribute(fp16_gemm, cudaFuncAttributeMaxDynamicSharedMemorySize,
                         GEMM_SMEM_BYTES);

    dim3 blk(256);
    const int smg = GEMM_SMEM_BYTES;

    // 0. convert weights to fp16
    cvt_kernel<<<(DIM * DIM / 4 + 255) / 256, blk>>>(q_w, qwh, DIM * DIM / 4);
    cvt_kernel<<<(NKVH * HD * DIM / 4 + 255) / 256, blk>>>(k_w, kwh, NKVH * HD * DIM / 4);
    cvt_kernel<<<(NKVH * HD * DIM / 4 + 255) / 256, blk>>>(v_w, vwh, NKVH * HD * DIM / 4);
    cvt_kernel<<<(DIM * DIM / 4 + 255) / 256, blk>>>(o_w, owh, DIM * DIM / 4);
    cvt_kernel<<<(FF * DIM / 4 + 255) / 256, blk>>>(gate_w, gwh, FF * DIM / 4);
    cvt_kernel<<<(FF * DIM / 4 + 255) / 256, blk>>>(up_w, uwh, FF * DIM / 4);
    cvt_kernel<<<(DIM * FF / 4 + 255) / 256, blk>>>(down_w, dwh, DIM * FF / 4);

    // 1. ln1 -> fp16
    rmsnorm_half_kernel<<<TOK, blk>>>(hidden, ln1, xnh);
    // 2-4. q/k/v projections
    fp16_gemm<<<dim3((NH * HD) / GBN, TOK / GBM), blk, smg>>>(xnh, qwh, q, (const float*)0, TOK, NH * HD, DIM, 0, 0, 0);
    fp16_gemm<<<dim3((NKVH * HD) / GBN, TOK / GBM), blk, smg>>>(xnh, kwh, k, (const float*)0, TOK, NKVH * HD, DIM, 0, 0, 0);
    fp16_gemm<<<dim3((NKVH * HD) / GBN, TOK / GBM), blk, smg>>>(xnh, vwh, v, (const float*)0, TOK, NKVH * HD, DIM, 0, 0, 0);
    // 5. RoPE
    rope_kernel<<<(TOK * NH * 64 + 255) / 256, blk>>>(q, NH);
    rope_kernel<<<(TOK * NKVH * 64 + 255) / 256, blk>>>(k, NKVH);
    // 6. attention -> fp16 plane
    attn_kernel<<<dim3(SEQ / 64, NH, BATCH), blk,
                  ATTN_SMEM_FLOATS * sizeof(float)>>>(q, k, v, ah);
    // 7. o-proj + residual
    fp16_gemm<<<dim3(DIM / GBN, TOK / GBM), blk, smg>>>(ah, owh, h, hidden, TOK, DIM, NH * HD, 0, 0, 0);
    // 8. ln2 -> fp16
    rmsnorm_half_kernel<<<TOK, blk>>>(h, ln2, hnh);
    // 9. MoD compaction
    compact_kernel<<<1, blk>>>(mask, tscore);
    // 10-11. gathered gate/up (dynamic M)
    fp16_gemm<<<dim3(FF / GBN, TOK / GBM), blk, smg>>>(hnh, gwh, gate, (const float*)0, TOK, FF, DIM, 1, 0, 1);
    fp16_gemm<<<dim3(FF / GBN, TOK / GBM), blk, smg>>>(hnh, uwh, up, (const float*)0, TOK, FF, DIM, 1, 0, 1);
    // 12. silu * up -> fp16 act
    silu_mul_kernel<<<2048, blk>>>(gate, up, acth);
    // 13. out = h
    copy_kernel<<<(TOK * DIM / 4 + 255) / 256, blk>>>(out, h);
    // 14. down-proj, scatter-add with per-token MoD scale
    fp16_gemm<<<dim3(DIM / GBN, TOK / GBM), blk, smg>>>(acth, dwh, out, (const float*)0, TOK, DIM, FF, 0, 1, 1);
}

// round 8
// speedup vs baseline: 6.4065x; 2.3293x over previous
#include <cuda_runtime.h>
#include <cuda_fp16.h>
#include <cuda_pipeline.h>
#include <mma.h>
#include <stdint.h>
#include <math.h>

using namespace nvcuda;

#define TOK 4096
#define DIM 2048
#define NH 16
#define NKVH 4
#define HD 128
#define FF 7168
#define SEQ 2048
#define BATCH 2

#define GBM 128
#define GBN 128
#define GBK 64
#define GLD 72
#define TILE_ELEMS (GBM * GLD)
#define STAGE_BYTES (2 * TILE_ELEMS * 2)
#define GEMM_SMEM_BYTES (2 * STAGE_BYTES)

// attention smem: Qs/Ks/Vs fp16 [64][136], Ps f32 [64][72], Ph fp16 [64][72],
// Os f32 [64][136], rowm/rowl/rowsc f32 [64]
#define ATTN_SMEM_BYTES (3 * 64 * 136 * 2 + 64 * 72 * 4 + 64 * 72 * 2 + 64 * 136 * 4 + 3 * 64 * 4)

// ---------------- scratch (static device globals; no allocation allowed) ---
__device__ float g_h[TOK * DIM];
__device__ int   g_idx[TOK];
__device__ float g_scale[TOK];
__device__ int   g_nsel;

// fp16 activation planes
__device__ __half g_xnh[TOK * DIM];
__device__ __half g_qh[TOK * NH * HD];
__device__ __half g_kh[TOK * NKVH * HD];
__device__ __half g_vh[TOK * NKVH * HD];
__device__ __half g_ah[TOK * DIM];
__device__ __half g_hnh[TOK * DIM];
__device__ __half g_gateh[TOK * FF];
__device__ __half g_uph[TOK * FF];
__device__ __half g_acth[TOK * FF];
// fp16 weight planes
__device__ __half g_qwh[DIM * DIM];
__device__ __half g_kwh[NKVH * HD * DIM];
__device__ __half g_vwh[NKVH * HD * DIM];
__device__ __half g_owh[DIM * DIM];
__device__ __half g_gwh[FF * DIM];
__device__ __half g_uwh[FF * DIM];
__device__ __half g_dwh[DIM * FF];

// ---------------- fp32 -> fp16 convert kernel ------------------------------
__global__ void cvt_kernel(const float* __restrict__ src,
                           __half* __restrict__ dst, int n4) {
    int i = blockIdx.x * blockDim.x + threadIdx.x;
    if (i >= n4) return;
    float4 v = ((const float4*)src)[i];
    __half2* hp = (__half2*)dst + i * 2;
    hp[0] = __floats2half2_rn(v.x, v.y);
    hp[1] = __floats2half2_rn(v.z, v.w);
}

// ---------------- fp16 GEMM: C[M,N] = A[M,K] @ W[N,K]^T --------------------
// fp16 operands, fp32 accumulate, cp.async double-buffered.
// Ch nonzero: plain fp16 store. Else fp32 C with Res/scatter modes.
__global__ __launch_bounds__(256)
void fp16_gemm(const __half* __restrict__ Ah, const __half* __restrict__ Wh,
               float* __restrict__ C, __half* __restrict__ Ch,
               const float* __restrict__ Res,
               int M, int N, int K, int gather, int scatter, int dynm) {
    const int Mreal = dynm ? g_nsel : M;
    const int bm = blockIdx.y * GBM;
    if (bm >= Mreal) return;
    const int bn = blockIdx.x * GBN;

    extern __shared__ char smraw[];

    const int tid = threadIdx.x;
    const int warp = tid >> 5;
    const int wm = (warp >> 1) * 32;
    const int wn = (warp & 1) * 64;

    const int cc = tid & 7;
    int lrow[4], arowg[4], wrowg[4];
    bool avalid[4];
    for (int t = 0; t < 4; t++) {
        int row = (tid >> 3) + t * 32;
        lrow[t] = row;
        int am = bm + row;
        avalid[t] = (am < Mreal);
        arowg[t] = avalid[t] ? (gather ? g_idx[am] : am) : 0;
        wrowg[t] = bn + row;
    }

    wmma::fragment<wmma::accumulator, 16, 16, 16, float> acc[2][4];
    for (int mt = 0; mt < 2; mt++)
        for (int nt = 0; nt < 4; nt++)
            wmma::fill_fragment(acc[mt][nt], 0.0f);

    const int nchunks = K / GBK;
    const uint4 zz = make_uint4(0u, 0u, 0u, 0u);

    for (int c = 0; c < nchunks + 1; c++) {
        if (c < nchunks) {
            char* sb = smraw + (c & 1) * STAGE_BYTES;
            __half* sA = (__half*)sb;
            __half* sW = sA + TILE_ELEMS;
            int k0 = c * GBK;
            for (int t = 0; t < 4; t++) {
                int so = lrow[t] * GLD + cc * 8;
                if (avalid[t]) {
                    size_t go = (size_t)arowg[t] * K + k0 + cc * 8;
                    __pipeline_memcpy_async(sA + so, Ah + go, 16);
                } else {
                    *(uint4*)(sA + so) = zz;
                }
                size_t wo = (size_t)wrowg[t] * K + k0 + cc * 8;
                __pipeline_memcpy_async(sW + so, Wh + wo, 16);
            }
            __pipeline_commit();
        }
        if (c > 0) {
            __pipeline_wait_prior(c < nchunks ? 1 : 0);
            __syncthreads();
            char* sb = smraw + ((c - 1) & 1) * STAGE_BYTES;
            const __half* sA = (const __half*)sb;
            const __half* sW = sA + TILE_ELEMS;
            for (int kc = 0; kc < GBK; kc += 16) {
                wmma::fragment<wmma::matrix_a, 16, 16, 16, __half, wmma::row_major> af[2];
                wmma::fragment<wmma::matrix_b, 16, 16, 16, __half, wmma::col_major> bf[4];
                for (int mt = 0; mt < 2; mt++)
                    wmma::load_matrix_sync(af[mt], sA + (wm + mt * 16) * GLD + kc, GLD);
                for (int nt = 0; nt < 4; nt++)
                    wmma::load_matrix_sync(bf[nt], sW + (wn + nt * 16) * GLD + kc, GLD);
                for (int mt = 0; mt < 2; mt++)
                    for (int nt = 0; nt < 4; nt++)
                        wmma::mma_sync(acc[mt][nt], af[mt], bf[nt], acc[mt][nt]);
            }
            __syncthreads();
        }
    }

    float* Cs = (float*)smraw;     // 128 x 136
    for (int mt = 0; mt < 2; mt++)
        for (int nt = 0; nt < 4; nt++)
            wmma::store_matrix_sync(Cs + (wm + mt * 16) * 136 + wn + nt * 16,
                                    acc[mt][nt], 136, wmma::mem_row_major);
    __syncthreads();

    {
        int r = tid >> 1;
        int c0 = (tid & 1) * 64;
        int row = bm + r;
        if (row < Mreal) {
            const float* cr = Cs + r * 136 + c0;
            if (Ch) {
                size_t off = (size_t)row * N + bn + c0;
                for (int j0 = 0; j0 < 64; j0 += 8) {
                    __half tmp[8];
                    for (int j = 0; j < 8; j++) tmp[j] = __float2half(cr[j0 + j]);
                    *(uint4*)(Ch + off + j0) = *(uint4*)tmp;
                }
            } else {
                int crow = scatter ? g_idx[row] : row;
                size_t off = (size_t)crow * N + bn + c0;
                if (scatter) {
                    float rs = g_scale[crow];
                    for (int j = 0; j < 64; j++) C[off + j] += rs * cr[j];
                } else if (Res) {
                    for (int j = 0; j < 64; j++) C[off + j] = Res[off + j] + cr[j];
                } else {
                    for (int j = 0; j < 64; j++) C[off + j] = cr[j];
                }
            }
        }
    }
}

// ---------------- RMSNorm (writes fp16 plane) -------------------------------
__global__ void rmsnorm_half_kernel(const float* __restrict__ x,
                                    const float* __restrict__ w,
                                    __half* __restrict__ oh) {
    const int row = blockIdx.x;
    const float* xr = x + (size_t)row * DIM;
    float ss = 0.f;
    for (int i = threadIdx.x; i < DIM; i += 256) {
        float v = xr[i];
        ss += v * v;
    }
    __shared__ float red[256];
    red[threadIdx.x] = ss;
    __syncthreads();
    for (int off = 128; off > 0; off >>= 1) {
        if (threadIdx.x < off) red[threadIdx.x] += red[threadIdx.x + off];
        __syncthreads();
    }
    float rs = rsqrtf(red[0] / (float)DIM + 1e-5f);
    for (int i = threadIdx.x; i < DIM; i += 256)
        oh[(size_t)row * DIM + i] = __float2half(xr[i] * rs * w[i]);
}

// ---------------- RoPE (in-place on fp16 plane) ----------------------------
__global__ void rope_half_kernel(__half* __restrict__ x, int nHeads) {
    int i = blockIdx.x * blockDim.x + threadIdx.x;
    int total = TOK * nHeads * 64;
    if (i >= total) return;
    int half = i & 63;
    int t = i >> 6;
    int hd = t % nHeads;
    int tok = t / nHeads;
    int pos = tok % SEQ;
    float inv = expf(-logf(10000.f) * (float)half * (1.f / 64.f));
    float ang = (float)pos * inv;
    float c = cosf(ang), s = sinf(ang);
    __half* base = x + (size_t)tok * (nHeads * HD) + hd * HD + half;
    float x1 = __half2float(base[0]), x2 = __half2float(base[64]);
    base[0] = __float2half(x1 * c - x2 * s);
    base[64] = __float2half(x2 * c + x1 * s);
}

// ---------------- WMMA flash attention (fp16 in, fp32 accum, causal, GQA) --
__global__ __launch_bounds__(256)
void attn_wmma(const __half* __restrict__ Qm, const __half* __restrict__ Km,
               const __half* __restrict__ Vm, __half* __restrict__ Om) {
    extern __shared__ char smb[];
    __half* Qs = (__half*)smb;             // [64][136]
    __half* Ks = Qs + 64 * 136;            // [64][136]
    __half* Vs = Ks + 64 * 136;            // [64][136]
    float*  Ps = (float*)(Vs + 64 * 136);  // [64][72]
    __half* Ph = (__half*)(Ps + 64 * 72);  // [64][72]
    float*  Os = (float*)(Ph + 64 * 72);   // [64][136]
    float* rowm = Os + 64 * 136;
    float* rowl = rowm + 64;
    float* rowsc = rowl + 64;

    const int tid = threadIdx.x;
    const int warp = tid >> 5;
    const int wq = warp >> 1;        // 0..3 row band (16 rows)
    const int wc = warp & 1;         // col half
    const int qt = blockIdx.x, h = blockIdx.y, b = blockIdx.z;
    const int kvh = h / (NH / NKVH);
    const int q0 = qt * 64;

    // load Q tile (fp16, 8-half chunks)
    for (int i = tid; i < 64 * 16; i += 256) {
        int r = i >> 4, ch = i & 15;
        *(uint4*)(Qs + r * 136 + ch * 8) =
            *(const uint4*)(Qm + (size_t)(b * SEQ + q0 + r) * (NH * HD) + h * HD + ch * 8);
    }
    // init O and stats
    for (int i = tid; i < 64 * 34; i += 256) {
        int r = i / 34, c = i % 34;
        *(float4*)(Os + r * 136 + c * 4) = make_float4(0.f, 0.f, 0.f, 0.f);
    }
    if (tid < 64) { rowm[tid] = -1e30f; rowl[tid] = 0.f; }

    const float qk_scale = 0.08838834764831845f;

    for (int kt = 0; kt <= qt; kt++) {
        __syncthreads();   // protect Vs/Ks from previous iteration's PV
        for (int i = tid; i < 64 * 16; i += 256) {
            int r = i >> 4, ch = i & 15;
            size_t off = (size_t)(b * SEQ + kt * 64 + r) * (NKVH * HD) + kvh * HD + ch * 8;
            *(uint4*)(Ks + r * 136 + ch * 8) = *(const uint4*)(Km + off);
            *(uint4*)(Vs + r * 136 + ch * 8) = *(const uint4*)(Vm + off);
        }
        __syncthreads();

        // ---- S = Q @ K^T (64x64), warp covers 16 rows x 32 cols ----
        {
            wmma::fragment<wmma::accumulator, 16, 16, 16, float> sfr[2];
            wmma::fill_fragment(sfr[0], 0.0f);
            wmma::fill_fragment(sfr[1], 0.0f);
            for (int kd = 0; kd < 128; kd += 16) {
                wmma::fragment<wmma::matrix_a, 16, 16, 16, __half, wmma::row_major> af;
                wmma::load_matrix_sync(af, Qs + wq * 16 * 136 + kd, 136);
                for (int nt = 0; nt < 2; nt++) {
                    wmma::fragment<wmma::matrix_b, 16, 16, 16, __half, wmma::col_major> bf;
                    wmma::load_matrix_sync(bf, Ks + (wc * 32 + nt * 16) * 136 + kd, 136);
                    wmma::mma_sync(sfr[nt], af, bf, sfr[nt]);
                }
            }
            for (int nt = 0; nt < 2; nt++)
                wmma::store_matrix_sync(Ps + wq * 16 * 72 + wc * 32 + nt * 16,
                                        sfr[nt], 72, wmma::mem_row_major);
        }
        __syncthreads();

        // ---- masked online softmax: 4 threads per row ----
        {
            int r = tid >> 2, sub = tid & 3;
            int gq = q0 + r;
            float m0 = rowm[r];
            float vals[16];
            float mx = m0;
            for (int c0 = 0; c0 < 16; c0++) {
                int c = sub * 16 + c0;
                int gk = kt * 64 + c;
                float v = Ps[r * 72 + c] * qk_scale;
                if (gk > gq) v = -1e30f;
                vals[c0] = v;
                mx = fmaxf(mx, v);
            }
            mx = fmaxf(mx, __shfl_xor_sync(0xffffffffu, mx, 1));
            mx = fmaxf(mx, __shfl_xor_sync(0xffffffffu, mx, 2));
            float sum = 0.f;
            for (int c0 = 0; c0 < 16; c0++) {
                float p = __expf(vals[c0] - mx);
                Ph[r * 72 + sub * 16 + c0] = __float2half(p);
                sum += p;
            }
            sum += __shfl_xor_sync(0xffffffffu, sum, 1);
            sum += __shfl_xor_sync(0xffffffffu, sum, 2);
            if (sub == 0) {
                float sc = __expf(m0 - mx);
                rowl[r] = rowl[r] * sc + sum;
                rowm[r] = mx;
                rowsc[r] = sc;
            }
        }
        __syncthreads();

        // ---- rescale O by per-row factor ----
        for (int i = tid; i < 64 * 32; i += 256) {
            int r = i >> 5, c4 = (i & 31) * 4;
            float s = rowsc[r];
            float4* p = (float4*)(Os + r * 136 + c4);
            float4 v = *p;
            v.x *= s; v.y *= s; v.z *= s; v.w *= s;
            *p = v;
        }
        __syncthreads();

        // ---- O += P @ V, warp covers 16 rows x 64 cols ----
        {
            wmma::fragment<wmma::matrix_a, 16, 16, 16, __half, wmma::row_major> af[4];
            for (int kk = 0; kk < 4; kk++)
                wmma::load_matrix_sync(af[kk], Ph + wq * 16 * 72 + kk * 16, 72);
            for (int nt = 0; nt < 4; nt++) {
                int col0 = wc * 64 + nt * 16;
                wmma::fragment<wmma::accumulator, 16, 16, 16, float> ofr;
                wmma::load_matrix_sync(ofr, Os + wq * 16 * 136 + col0, 136, wmma::mem_row_major);
                for (int kk = 0; kk < 4; kk++) {
                    wmma::fragment<wmma::matrix_b, 16, 16, 16, __half, wmma::row_major> bf;
                    wmma::load_matrix_sync(bf, Vs + kk * 16 * 136 + col0, 136);
                    wmma::mma_sync(ofr, af[kk], bf, ofr);
                }
                wmma::store_matrix_sync(Os + wq * 16 * 136 + col0, ofr, 136, wmma::mem_row_major);
            }
        }
    }
    __syncthreads();

    // ---- final normalize + fp16 store ----
    for (int i = tid; i < 64 * 16; i += 256) {
        int r = i >> 4, ch = i & 15;
        float inv = 1.f / rowl[r];
        __half tmp[8];
        for (int j = 0; j < 8; j++)
            tmp[j] = __float2half(Os[r * 136 + ch * 8 + j] * inv);
        *(uint4*)(Om + (size_t)(b * SEQ + q0 + r) * (NH * HD) + h * HD + ch * 8) = *(uint4*)tmp;
    }
}

// ---------------- MoD compaction (single block, deterministic) ------------
__global__ void compact_kernel(const int* __restrict__ mask,
                               const float* __restrict__ scores) {
    __shared__ int ssum[256];
    __shared__ int base;
    const int t = threadIdx.x;
    if (t == 0) base = 0;
    __syncthreads();
    for (int start = 0; start < TOK; start += 256) {
        int i = start + t;
        int f = (mask[i] != 0) ? 1 : 0;
        g_scale[i] = 0.5f + (scores[i] - 0.5f) * 0.7f;
        ssum[t] = f;
        __syncthreads();
        for (int off = 1; off < 256; off <<= 1) {
            int v = (t >= off) ? ssum[t - off] : 0;
            __syncthreads();
            ssum[t] += v;
            __syncthreads();
        }
        if (f) g_idx[base + ssum[t] - 1] = i;
        __syncthreads();
        if (t == 0) base += ssum[255];
        __syncthreads();
    }
    if (t == 0) g_nsel = base;
}

// ---------------- SiLU(gate) * up (fp16 in/out, dynamic rows) --------------
__global__ void silu_mul_kernel(const __half* __restrict__ gate,
                                const __half* __restrict__ up,
                                __half* __restrict__ acth) {
    size_t total = (size_t)g_nsel * FF;
    size_t stride = (size_t)gridDim.x * blockDim.x;
    for (size_t i = (size_t)blockIdx.x * blockDim.x + threadIdx.x; i < total; i += stride) {
        float g = __half2float(gate[i]);
        float u = __half2float(up[i]);
        acth[i] = __float2half((g / (1.f + __expf(-g))) * u);
    }
}

// ---------------- residual copy to output ---------------------------------
__global__ void copy_kernel(float* __restrict__ dst, const float* __restrict__ src) {
    int i = blockIdx.x * blockDim.x + threadIdx.x;
    if (i < TOK * DIM / 4)
        ((float4*)dst)[i] = ((const float4*)src)[i];
}

// ---------------- driver ---------------------------------------------------
extern "C" void kernel_launch(void* const* d_in, const int* in_sizes, int n_in,
                              void* d_out, int out_size) {
    const float* hidden = (const float*)d_in[0];
    const int* mask = (const int*)d_in[1];
    const float* tscore = (const float*)d_in[2];
    const float* ln1 = (const float*)d_in[3];
    const float* ln2 = (const float*)d_in[4];
    const float* q_w = (const float*)d_in[5];
    const float* k_w = (const float*)d_in[6];
    const float* v_w = (const float*)d_in[7];
    const float* o_w = (const float*)d_in[8];
    const float* gate_w = (const float*)d_in[9];
    const float* up_w = (const float*)d_in[10];
    const float* down_w = (const float*)d_in[11];
    float* out = (float*)d_out;

    void* p;
    cudaGetSymbolAddress(&p, g_h);     float* h = (float*)p;
    __half *xnh, *qh, *kh, *vh, *ah, *hnh, *gateh, *uph, *acth;
    __half *qwh, *kwh, *vwh, *owh, *gwh, *uwh, *dwh;
    cudaGetSymbolAddress(&p, g_xnh);   xnh = (__half*)p;
    cudaGetSymbolAddress(&p, g_qh);    qh = (__half*)p;
    cudaGetSymbolAddress(&p, g_kh);    kh = (__half*)p;
    cudaGetSymbolAddress(&p, g_vh);    vh = (__half*)p;
    cudaGetSymbolAddress(&p, g_ah);    ah = (__half*)p;
    cudaGetSymbolAddress(&p, g_hnh);   hnh = (__half*)p;
    cudaGetSymbolAddress(&p, g_gateh); gateh = (__half*)p;
    cudaGetSymbolAddress(&p, g_uph);   uph = (__half*)p;
    cudaGetSymbolAddress(&p, g_acth);  acth = (__half*)p;
    cudaGetSymbolAddress(&p, g_qwh);   qwh = (__half*)p;
    cudaGetSymbolAddress(&p, g_kwh);   kwh = (__half*)p;
    cudaGetSymbolAddress(&p, g_vwh);   vwh = (__half*)p;
    cudaGetSymbolAddress(&p, g_owh);   owh = (__half*)p;
    cudaGetSymbolAddress(&p, g_gwh);   gwh = (__half*)p;
    cudaGetSymbolAddress(&p, g_uwh);   uwh = (__half*)p;
    cudaGetSymbolAddress(&p, g_dwh);   dwh = (__half*)p;

    cudaFuncSetAttribute(fp16_gemm, cudaFuncAttributeMaxDynamicSharedMemorySize,
                         GEMM_SMEM_BYTES);
    cudaFuncSetAttribute(attn_wmma, cudaFuncAttributeMaxDynamicSharedMemorySize,
                         ATTN_SMEM_BYTES);

    dim3 blk(256);
    const int smg = GEMM_SMEM_BYTES;

    // 0. convert weights to fp16
    cvt_kernel<<<(DIM * DIM / 4 + 255) / 256, blk>>>(q_w, qwh, DIM * DIM / 4);
    cvt_kernel<<<(NKVH * HD * DIM / 4 + 255) / 256, blk>>>(k_w, kwh, NKVH * HD * DIM / 4);
    cvt_kernel<<<(NKVH * HD * DIM / 4 + 255) / 256, blk>>>(v_w, vwh, NKVH * HD * DIM / 4);
    cvt_kernel<<<(DIM * DIM / 4 + 255) / 256, blk>>>(o_w, owh, DIM * DIM / 4);
    cvt_kernel<<<(FF * DIM / 4 + 255) / 256, blk>>>(gate_w, gwh, FF * DIM / 4);
    cvt_kernel<<<(FF * DIM / 4 + 255) / 256, blk>>>(up_w, uwh, FF * DIM / 4);
    cvt_kernel<<<(DIM * FF / 4 + 255) / 256, blk>>>(down_w, dwh, DIM * FF / 4);

    // 1. ln1 -> fp16
    rmsnorm_half_kernel<<<TOK, blk>>>(hidden, ln1, xnh);
    // 2-4. q/k/v projections -> fp16 planes
    fp16_gemm<<<dim3((NH * HD) / GBN, TOK / GBM), blk, smg>>>(xnh, qwh, (float*)0, qh, (const float*)0, TOK, NH * HD, DIM, 0, 0, 0);
    fp16_gemm<<<dim3((NKVH * HD) / GBN, TOK / GBM), blk, smg>>>(xnh, kwh, (float*)0, kh, (const float*)0, TOK, NKVH * HD, DIM, 0, 0, 0);
    fp16_gemm<<<dim3((NKVH * HD) / GBN, TOK / GBM), blk, smg>>>(xnh, vwh, (float*)0, vh, (const float*)0, TOK, NKVH * HD, DIM, 0, 0, 0);
    // 5. RoPE in-place on fp16
    rope_half_kernel<<<(TOK * NH * 64 + 255) / 256, blk>>>(qh, NH);
    rope_half_kernel<<<(TOK * NKVH * 64 + 255) / 256, blk>>>(kh, NKVH);
    // 6. tensor-core attention -> ah fp16
    attn_wmma<<<dim3(SEQ / 64, NH, BATCH), blk, ATTN_SMEM_BYTES>>>(qh, kh, vh, ah);
    // 7. o-proj + residual -> h fp32
    fp16_gemm<<<dim3(DIM / GBN, TOK / GBM), blk, smg>>>(ah, owh, h, (__half*)0, hidden, TOK, DIM, NH * HD, 0, 0, 0);
    // 8. ln2 -> fp16
    rmsnorm_half_kernel<<<TOK, blk>>>(h, ln2, hnh);
    // 9. MoD compaction
    compact_kernel<<<1, blk>>>(mask, tscore);
    // 10-11. gathered gate/up -> fp16 planes (dynamic M)
    fp16_gemm<<<dim3(FF / GBN, TOK / GBM), blk, smg>>>(hnh, gwh, (float*)0, gateh, (const float*)0, TOK, FF, DIM, 1, 0, 1);
    fp16_gemm<<<dim3(FF / GBN, TOK / GBM), blk, smg>>>(hnh, uwh, (float*)0, uph, (const float*)0, TOK, FF, DIM, 1, 0, 1);
    // 12. silu * up -> fp16 act
    silu_mul_kernel<<<2048, blk>>>(gateh, uph, acth);
    // 13. out = h
    copy_kernel<<<(TOK * DIM / 4 + 255) / 256, blk>>>(out, h);
    // 14. down-proj, scatter-add with per-token MoD scale
    fp16_gemm<<<dim3(DIM / GBN, TOK / GBM), blk, smg>>>(acth, dwh, out, (__half*)0, (const float*)0, TOK, DIM, FF, 0, 1, 1);
}